// round 1
// baseline (speedup 1.0000x reference)
#include <cuda_runtime.h>
#include <math.h>

// Problem dims (fixed per metadata):
//  x      [2,1024,1024] f32   -> T=2048 tokens, H=1024
//  gate_w [1024,8] f32
//  gate_b [8] f32
//  w1     [8,1024,2048] f32   (E,H,I)
//  w3     [8,1024,2048] f32
//  w2     [8,2048,1024] f32   (E,I,H)
//  out    [2,1024,1024] f32
#define T_TOK 2048
#define HDIM  1024
#define IDIM  2048
#define NEXP  8
#define TOPK  2

// ---------------- device scratch (no allocs allowed) ----------------
__device__ int   g_counts[NEXP];
__device__ int   g_offsets[NEXP];
__device__ int   g_tok [NEXP * T_TOK];
__device__ float g_wt  [NEXP * T_TOK];
__device__ int   g_slot[NEXP * T_TOK];
__device__ float g_h[(size_t)TOPK * T_TOK * IDIM];          // 4096 x 2048 packed rows
__device__ float g_slotbuf[(size_t)TOPK * T_TOK * HDIM];    // [slot][token][H]

// ---------------- kernel 0: zero counts ----------------
__global__ void k_zero_counts() {
    if (threadIdx.x < NEXP) g_counts[threadIdx.x] = 0;
}

// ---------------- kernel 1: gating (one warp per token) ----------------
__global__ void k_gate(const float* __restrict__ x,
                       const float* __restrict__ gw,
                       const float* __restrict__ gb) {
    int warp = (blockIdx.x * blockDim.x + threadIdx.x) >> 5;
    int lane = threadIdx.x & 31;
    if (warp >= T_TOK) return;
    const float* xr = x + (size_t)warp * HDIM;

    float acc[NEXP];
#pragma unroll
    for (int e = 0; e < NEXP; ++e) acc[e] = 0.f;

    for (int h = lane; h < HDIM; h += 32) {
        float xv = xr[h];
        const float4* g4 = (const float4*)(gw + (size_t)h * NEXP);
        float4 a = g4[0], b = g4[1];
        acc[0] += xv * a.x; acc[1] += xv * a.y;
        acc[2] += xv * a.z; acc[3] += xv * a.w;
        acc[4] += xv * b.x; acc[5] += xv * b.y;
        acc[6] += xv * b.z; acc[7] += xv * b.w;
    }
#pragma unroll
    for (int o = 16; o > 0; o >>= 1) {
#pragma unroll
        for (int e = 0; e < NEXP; ++e)
            acc[e] += __shfl_xor_sync(0xffffffffu, acc[e], o);
    }
    if (lane == 0) {
        float l[NEXP];
        float m = -1e30f;
#pragma unroll
        for (int e = 0; e < NEXP; ++e) { l[e] = acc[e] + gb[e]; m = fmaxf(m, l[e]); }
        float p[NEXP];
#pragma unroll
        for (int e = 0; e < NEXP; ++e) p[e] = expf(l[e] - m);
        // top-2 (first occurrence on ties, matching jax top_k)
        int i0 = 0;
#pragma unroll
        for (int e = 1; e < NEXP; ++e) if (p[e] > p[i0]) i0 = e;
        int i1 = (i0 == 0) ? 1 : 0;
#pragma unroll
        for (int e = 0; e < NEXP; ++e) if (e != i0 && p[e] > p[i1]) i1 = e;
        float s = p[i0] + p[i1];
        float w0 = p[i0] / s, w1 = p[i1] / s;

        int p0 = atomicAdd(&g_counts[i0], 1);
        g_tok [i0 * T_TOK + p0] = warp;
        g_wt  [i0 * T_TOK + p0] = w0;
        g_slot[i0 * T_TOK + p0] = 0;
        int p1 = atomicAdd(&g_counts[i1], 1);
        g_tok [i1 * T_TOK + p1] = warp;
        g_wt  [i1 * T_TOK + p1] = w1;
        g_slot[i1 * T_TOK + p1] = 1;
    }
}

// ---------------- kernel 2: exclusive prefix of counts ----------------
__global__ void k_offsets() {
    if (threadIdx.x == 0) {
        int off = 0;
        for (int e = 0; e < NEXP; ++e) { g_offsets[e] = off; off += g_counts[e]; }
    }
}

// ---------------- GEMM tiling ----------------
#define BM 64
#define BN 64
#define BK 16
#define APAD 4   // As stride = BK+APAD = 20 (keeps float4 stores aligned)

// kernel 3: h = silu(Xg @ w1[e]) * (Xg @ w3[e])   (gathered rows)
__global__ void __launch_bounds__(256, 2)
k_gemm1(const float* __restrict__ x,
        const float* __restrict__ w1,
        const float* __restrict__ w3) {
    int e  = blockIdx.z;
    int mt = blockIdx.y;
    int nt = blockIdx.x;
    int M  = g_counts[e];
    if (mt * BM >= M) return;
    int base = g_offsets[e];

    __shared__ float As[BM][BK + APAD];
    __shared__ float B1s[BK][BN];
    __shared__ float B3s[BK][BN];
    __shared__ int   toks[BM];

    int tid = threadIdx.x;          // 256
    if (tid < BM) {
        int r = mt * BM + tid;
        toks[tid] = (r < M) ? g_tok[e * T_TOK + r] : -1;
    }
    __syncthreads();

    const float* W1 = w1 + (size_t)e * HDIM * IDIM;
    const float* W3 = w3 + (size_t)e * HDIM * IDIM;

    int tx = tid & 15, ty = tid >> 4;
    int ty4 = ty * 4, tx4 = tx * 4;

    int arow = tid >> 2;            // 0..63
    int ac4  = (tid & 3) * 4;       // 0,4,8,12
    int atok = toks[arow];
    int brow = tid >> 4;            // 0..15
    int bc4  = (tid & 15) * 4;      // 0..60

    float acc1[4][4], acc3[4][4];
#pragma unroll
    for (int i = 0; i < 4; ++i)
#pragma unroll
        for (int j = 0; j < 4; ++j) { acc1[i][j] = 0.f; acc3[i][j] = 0.f; }

    for (int k0 = 0; k0 < HDIM; k0 += BK) {
        float4 av = make_float4(0.f, 0.f, 0.f, 0.f);
        if (atok >= 0)
            av = *(const float4*)(x + (size_t)atok * HDIM + k0 + ac4);
        *(float4*)&As[arow][ac4] = av;
        *(float4*)&B1s[brow][bc4] =
            *(const float4*)(W1 + (size_t)(k0 + brow) * IDIM + nt * BN + bc4);
        *(float4*)&B3s[brow][bc4] =
            *(const float4*)(W3 + (size_t)(k0 + brow) * IDIM + nt * BN + bc4);
        __syncthreads();

#pragma unroll
        for (int k = 0; k < BK; ++k) {
            float a0 = As[ty4 + 0][k];
            float a1 = As[ty4 + 1][k];
            float a2 = As[ty4 + 2][k];
            float a3 = As[ty4 + 3][k];
            float4 b1 = *(const float4*)&B1s[k][tx4];
            float4 b3 = *(const float4*)&B3s[k][tx4];
            acc1[0][0] += a0 * b1.x; acc1[0][1] += a0 * b1.y; acc1[0][2] += a0 * b1.z; acc1[0][3] += a0 * b1.w;
            acc1[1][0] += a1 * b1.x; acc1[1][1] += a1 * b1.y; acc1[1][2] += a1 * b1.z; acc1[1][3] += a1 * b1.w;
            acc1[2][0] += a2 * b1.x; acc1[2][1] += a2 * b1.y; acc1[2][2] += a2 * b1.z; acc1[2][3] += a2 * b1.w;
            acc1[3][0] += a3 * b1.x; acc1[3][1] += a3 * b1.y; acc1[3][2] += a3 * b1.z; acc1[3][3] += a3 * b1.w;
            acc3[0][0] += a0 * b3.x; acc3[0][1] += a0 * b3.y; acc3[0][2] += a0 * b3.z; acc3[0][3] += a0 * b3.w;
            acc3[1][0] += a1 * b3.x; acc3[1][1] += a1 * b3.y; acc3[1][2] += a1 * b3.z; acc3[1][3] += a1 * b3.w;
            acc3[2][0] += a2 * b3.x; acc3[2][1] += a2 * b3.y; acc3[2][2] += a2 * b3.z; acc3[2][3] += a2 * b3.w;
            acc3[3][0] += a3 * b3.x; acc3[3][1] += a3 * b3.y; acc3[3][2] += a3 * b3.z; acc3[3][3] += a3 * b3.w;
        }
        __syncthreads();
    }

    // epilogue: h = c1 * sigmoid(c1) * c3
#pragma unroll
    for (int i = 0; i < 4; ++i) {
        int r = mt * BM + ty4 + i;
        if (r < M) {
            float4 hv;
            float c;
            c = acc1[i][0]; hv.x = c / (1.f + expf(-c)) * acc3[i][0];
            c = acc1[i][1]; hv.y = c / (1.f + expf(-c)) * acc3[i][1];
            c = acc1[i][2]; hv.z = c / (1.f + expf(-c)) * acc3[i][2];
            c = acc1[i][3]; hv.w = c / (1.f + expf(-c)) * acc3[i][3];
            *(float4*)(g_h + (size_t)(base + r) * IDIM + nt * BN + tx4) = hv;
        }
    }
}

// kernel 4: y = (h @ w2[e]) * weight  -> scatter into slot buffers
__global__ void __launch_bounds__(256, 2)
k_gemm2(const float* __restrict__ w2) {
    int e  = blockIdx.z;
    int mt = blockIdx.y;
    int nt = blockIdx.x;
    int M  = g_counts[e];
    if (mt * BM >= M) return;
    int base = g_offsets[e];

    __shared__ float As[BM][BK + APAD];
    __shared__ float Bs[BK][BN];

    int tid = threadIdx.x;
    const float* W2 = w2 + (size_t)e * IDIM * HDIM;

    int tx = tid & 15, ty = tid >> 4;
    int ty4 = ty * 4, tx4 = tx * 4;

    int arow = tid >> 2;
    int ac4  = (tid & 3) * 4;
    int brow = tid >> 4;
    int bc4  = (tid & 15) * 4;
    int aR   = mt * BM + arow;
    const float* arow_ptr = (aR < M) ? (g_h + (size_t)(base + aR) * IDIM) : nullptr;

    float acc[4][4];
#pragma unroll
    for (int i = 0; i < 4; ++i)
#pragma unroll
        for (int j = 0; j < 4; ++j) acc[i][j] = 0.f;

    for (int k0 = 0; k0 < IDIM; k0 += BK) {
        float4 av = make_float4(0.f, 0.f, 0.f, 0.f);
        if (arow_ptr) av = *(const float4*)(arow_ptr + k0 + ac4);
        *(float4*)&As[arow][ac4] = av;
        *(float4*)&Bs[brow][bc4] =
            *(const float4*)(W2 + (size_t)(k0 + brow) * HDIM + nt * BN + bc4);
        __syncthreads();

#pragma unroll
        for (int k = 0; k < BK; ++k) {
            float a0 = As[ty4 + 0][k];
            float a1 = As[ty4 + 1][k];
            float a2 = As[ty4 + 2][k];
            float a3 = As[ty4 + 3][k];
            float4 b = *(const float4*)&Bs[k][tx4];
            acc[0][0] += a0 * b.x; acc[0][1] += a0 * b.y; acc[0][2] += a0 * b.z; acc[0][3] += a0 * b.w;
            acc[1][0] += a1 * b.x; acc[1][1] += a1 * b.y; acc[1][2] += a1 * b.z; acc[1][3] += a1 * b.w;
            acc[2][0] += a2 * b.x; acc[2][1] += a2 * b.y; acc[2][2] += a2 * b.z; acc[2][3] += a2 * b.w;
            acc[3][0] += a3 * b.x; acc[3][1] += a3 * b.y; acc[3][2] += a3 * b.z; acc[3][3] += a3 * b.w;
        }
        __syncthreads();
    }

#pragma unroll
    for (int i = 0; i < 4; ++i) {
        int r = mt * BM + ty4 + i;
        if (r < M) {
            int   tok  = g_tok [e * T_TOK + r];
            float wt   = g_wt  [e * T_TOK + r];
            int   slot = g_slot[e * T_TOK + r];
            float4 v;
            v.x = wt * acc[i][0]; v.y = wt * acc[i][1];
            v.z = wt * acc[i][2]; v.w = wt * acc[i][3];
            *(float4*)(g_slotbuf + (size_t)slot * T_TOK * HDIM
                       + (size_t)tok * HDIM + nt * BN + tx4) = v;
        }
    }
}

// ---------------- kernel 5: combine slots ----------------
__global__ void k_combine(float* __restrict__ out) {
    size_t i = (size_t)blockIdx.x * blockDim.x + threadIdx.x;
    size_t n4 = (size_t)T_TOK * HDIM / 4;
    if (i >= n4) return;
    const float4* s0 = (const float4*)g_slotbuf;
    const float4* s1 = (const float4*)(g_slotbuf + (size_t)T_TOK * HDIM);
    float4 a = s0[i], b = s1[i];
    float4 r;
    r.x = a.x + b.x; r.y = a.y + b.y; r.z = a.z + b.z; r.w = a.w + b.w;
    ((float4*)out)[i] = r;
}

// ---------------- launcher ----------------
extern "C" void kernel_launch(void* const* d_in, const int* in_sizes, int n_in,
                              void* d_out, int out_size) {
    const float* x  = (const float*)d_in[0];
    const float* gw = (const float*)d_in[1];
    const float* gb = (const float*)d_in[2];
    const float* w1 = (const float*)d_in[3];
    const float* w3 = (const float*)d_in[4];
    const float* w2 = (const float*)d_in[5];
    float* out = (float*)d_out;

    k_zero_counts<<<1, 32>>>();
    k_gate<<<(T_TOK * 32 + 255) / 256, 256>>>(x, gw, gb);
    k_offsets<<<1, 32>>>();

    dim3 g1(IDIM / BN, T_TOK / BM, NEXP);   // (32, 32, 8)
    k_gemm1<<<g1, 256>>>(x, w1, w3);

    dim3 g2(HDIM / BN, T_TOK / BM, NEXP);   // (16, 32, 8)
    k_gemm2<<<g2, 256>>>(w2);

    size_t n4 = (size_t)T_TOK * HDIM / 4;
    k_combine<<<(unsigned)((n4 + 255) / 256), 256>>>(out);
}

// round 5
// speedup vs baseline: 2.1573x; 2.1573x over previous
#include <cuda_runtime.h>
#include <cuda_bf16.h>
#include <cstdint>
#include <math.h>

// dims
#define T_TOK 2048
#define HDIM  1024
#define IDIM  2048
#define NEXP  8

// ================= device scratch =================
__device__ int   g_counts[NEXP];
__device__ int   g_offsets[NEXP];
__device__ int   g_tok [NEXP * T_TOK];
__device__ float g_wt  [NEXP * T_TOK];
__device__ int   g_slot[NEXP * T_TOK];

// transposed split weights: w1t/w3t: [E][I][H] K-major ; w2t: [E][H][I]
__device__ __nv_bfloat16 g_w1t_hi[(size_t)NEXP * IDIM * HDIM];
__device__ __nv_bfloat16 g_w1t_lo[(size_t)NEXP * IDIM * HDIM];
__device__ __nv_bfloat16 g_w3t_hi[(size_t)NEXP * IDIM * HDIM];
__device__ __nv_bfloat16 g_w3t_lo[(size_t)NEXP * IDIM * HDIM];
__device__ __nv_bfloat16 g_w2t_hi[(size_t)NEXP * HDIM * IDIM];
__device__ __nv_bfloat16 g_w2t_lo[(size_t)NEXP * HDIM * IDIM];

// intermediate h (packed routed rows), pre-split to bf16 hi/lo
__device__ __nv_bfloat16 g_h_hi[(size_t)2 * T_TOK * IDIM];
__device__ __nv_bfloat16 g_h_lo[(size_t)2 * T_TOK * IDIM];
__device__ float g_slotbuf[(size_t)2 * T_TOK * HDIM];

// ================= helpers =================
__device__ __forceinline__ uint32_t smem_u32(const void* p) {
    uint32_t a;
    asm("{ .reg .u64 t; cvta.to.shared.u64 t, %1; cvt.u32.u64 %0, t; }" : "=r"(a) : "l"(p));
    return a;
}

#define LDMX4(r0, r1, r2, r3, addr)                                              \
    asm volatile("ldmatrix.sync.aligned.m8n8.x4.shared.b16 {%0,%1,%2,%3}, [%4];" \
                 : "=r"(r0), "=r"(r1), "=r"(r2), "=r"(r3) : "r"(addr))

__device__ __forceinline__ void mma_bf16(float* d, const uint32_t* a, uint32_t b0, uint32_t b1) {
    asm volatile(
        "mma.sync.aligned.m16n8k16.row.col.f32.bf16.bf16.f32 "
        "{%0,%1,%2,%3}, {%4,%5,%6,%7}, {%8,%9}, {%0,%1,%2,%3};"
        : "+f"(d[0]), "+f"(d[1]), "+f"(d[2]), "+f"(d[3])
        : "r"(a[0]), "r"(a[1]), "r"(a[2]), "r"(a[3]), "r"(b0), "r"(b1));
}

__device__ __forceinline__ void split2(float a, float b, uint32_t& hi, uint32_t& lo) {
    __nv_bfloat16 ha = __float2bfloat16_rn(a), hb = __float2bfloat16_rn(b);
    float ra = a - __bfloat162float(ha), rb = b - __bfloat162float(hb);
    __nv_bfloat162 hp; hp.x = ha; hp.y = hb;
    __nv_bfloat162 lp; lp.x = __float2bfloat16_rn(ra); lp.y = __float2bfloat16_rn(rb);
    hi = *(uint32_t*)&hp; lo = *(uint32_t*)&lp;
}

// ================= gating =================
__global__ void k_zero_counts() { if (threadIdx.x < NEXP) g_counts[threadIdx.x] = 0; }

__global__ void k_gate(const float* __restrict__ x, const float* __restrict__ gw,
                       const float* __restrict__ gb) {
    int warp = (blockIdx.x * blockDim.x + threadIdx.x) >> 5;
    int lane = threadIdx.x & 31;
    if (warp >= T_TOK) return;
    const float* xr = x + (size_t)warp * HDIM;
    float acc[NEXP];
#pragma unroll
    for (int e = 0; e < NEXP; ++e) acc[e] = 0.f;
    for (int h = lane; h < HDIM; h += 32) {
        float xv = xr[h];
        const float4* g4 = (const float4*)(gw + (size_t)h * NEXP);
        float4 a = g4[0], b = g4[1];
        acc[0] += xv * a.x; acc[1] += xv * a.y; acc[2] += xv * a.z; acc[3] += xv * a.w;
        acc[4] += xv * b.x; acc[5] += xv * b.y; acc[6] += xv * b.z; acc[7] += xv * b.w;
    }
#pragma unroll
    for (int o = 16; o > 0; o >>= 1)
#pragma unroll
        for (int e = 0; e < NEXP; ++e) acc[e] += __shfl_xor_sync(0xffffffffu, acc[e], o);
    if (lane == 0) {
        float l[NEXP]; float m = -1e30f;
#pragma unroll
        for (int e = 0; e < NEXP; ++e) { l[e] = acc[e] + gb[e]; m = fmaxf(m, l[e]); }
        float p[NEXP];
#pragma unroll
        for (int e = 0; e < NEXP; ++e) p[e] = expf(l[e] - m);
        int i0 = 0;
#pragma unroll
        for (int e = 1; e < NEXP; ++e) if (p[e] > p[i0]) i0 = e;
        int i1 = (i0 == 0) ? 1 : 0;
#pragma unroll
        for (int e = 0; e < NEXP; ++e) if (e != i0 && p[e] > p[i1]) i1 = e;
        float s = p[i0] + p[i1];
        int p0 = atomicAdd(&g_counts[i0], 1);
        g_tok[i0 * T_TOK + p0] = warp; g_wt[i0 * T_TOK + p0] = p[i0] / s; g_slot[i0 * T_TOK + p0] = 0;
        int p1 = atomicAdd(&g_counts[i1], 1);
        g_tok[i1 * T_TOK + p1] = warp; g_wt[i1 * T_TOK + p1] = p[i1] / s; g_slot[i1 * T_TOK + p1] = 1;
    }
}

__global__ void k_offsets() {
    if (threadIdx.x == 0) {
        int off = 0;
        for (int e = 0; e < NEXP; ++e) { g_offsets[e] = off; off += g_counts[e]; }
    }
}

// ================= split + transpose: [K,N] f32 -> [N,K] bf16 hi/lo =================
__global__ void k_split_transpose(const float* __restrict__ src,
                                  __nv_bfloat16* __restrict__ dhi,
                                  __nv_bfloat16* __restrict__ dlo,
                                  int K, int N) {
    __shared__ float tile[64][33];
    int e = blockIdx.z;
    const float* s = src + (size_t)e * K * N;
    __nv_bfloat16* oh = dhi + (size_t)e * K * N;
    __nv_bfloat16* ol = dlo + (size_t)e * K * N;
    int k0 = blockIdx.y * 64, n0 = blockIdx.x * 32;
    int tx = threadIdx.x & 31, ty = threadIdx.x >> 5;
#pragma unroll
    for (int kk = ty; kk < 64; kk += 8)
        tile[kk][tx] = s[(size_t)(k0 + kk) * N + n0 + tx];
    __syncthreads();
#pragma unroll
    for (int r = ty; r < 32; r += 8) {
        float v0 = tile[2 * tx][r], v1 = tile[2 * tx + 1][r];
        uint32_t hi, lo; split2(v0, v1, hi, lo);
        size_t base = (size_t)(n0 + r) * K + k0;
        ((uint32_t*)(oh + base))[tx] = hi;
        ((uint32_t*)(ol + base))[tx] = lo;
    }
}

// ================= mma.sync GEMM tiling =================
// CTA tile: 128(M) x 64(N), BK=32. 8 warps as 4(M) x 2(N); warp tile 32x32.
// smem rows padded to 80B (32 bf16 data + 16B pad) -> conflict-free ldmatrix.
#define AST 80

// -------- GEMM1: c1 = Xg @ w1', c3 = Xg @ w3' ; h = silu(c1)*c3 --------
__global__ void __launch_bounds__(256, 2)
k_gemm1_mma(const float* __restrict__ x) {
    __shared__ __align__(16) unsigned char sAh[128 * AST];
    __shared__ __align__(16) unsigned char sAl[128 * AST];
    __shared__ __align__(16) unsigned char sB[4][64 * AST];  // b1h, b1l, b3h, b3l
    __shared__ int toks[128];

    int e = blockIdx.z, mt = blockIdx.y, nt = blockIdx.x;
    int M = g_counts[e];
    if (mt * 128 >= M) return;
    int base = g_offsets[e];
    int tid = threadIdx.x;

    if (tid < 128) {
        int r = mt * 128 + tid;
        toks[tid] = (r < M) ? g_tok[e * T_TOK + r] : -1;
    }
    __syncthreads();

    const __nv_bfloat16* Bsrc[4];
    Bsrc[0] = g_w1t_hi + (size_t)e * IDIM * HDIM;
    Bsrc[1] = g_w1t_lo + (size_t)e * IDIM * HDIM;
    Bsrc[2] = g_w3t_hi + (size_t)e * IDIM * HDIM;
    Bsrc[3] = g_w3t_lo + (size_t)e * IDIM * HDIM;

    // loader indices
    int arow = tid >> 1;               // 0..127
    int acg  = (tid & 1) * 16;         // fp32 col group of 16
    int tokA = toks[arow];
    const float* xrow = (tokA >= 0) ? (x + (size_t)tokA * HDIM) : (const float*)0;

    int brr  = tid >> 2;               // 0..63
    int bseg = (tid & 3) * 8;          // 8 bf16 = 16B

    // mma indices
    int wid = tid >> 5, lane = tid & 31;
    int wm = wid >> 1, wn = wid & 1;
    uint32_t aLdHi = smem_u32(sAh) + (uint32_t)((wm * 32 + (lane & 15)) * AST + (lane >> 4) * 16);
    uint32_t aLdLo = smem_u32(sAl) + (uint32_t)((wm * 32 + (lane & 15)) * AST + (lane >> 4) * 16);
    int n_l = (lane & 7) + ((lane >> 4) << 3);
    uint32_t bOff = (uint32_t)((wn * 32 + n_l) * AST + ((lane >> 3) & 1) * 16);
    uint32_t bLd[4];
#pragma unroll
    for (int i = 0; i < 4; ++i) bLd[i] = smem_u32(sB[i]) + bOff;

    float c1[2][4][4], c3[2][4][4];
#pragma unroll
    for (int i = 0; i < 2; ++i)
#pragma unroll
        for (int g = 0; g < 4; ++g)
#pragma unroll
            for (int r = 0; r < 4; ++r) { c1[i][g][r] = 0.f; c3[i][g][r] = 0.f; }

    for (int cch = 0; cch < HDIM / 32; ++cch) {
        int k0 = cch * 32;
        // ---- A: gather fp32, split -> smem hi/lo ----
        {
            float4 v0, v1, v2, v3;
            if (xrow) {
                const float4* p = (const float4*)(xrow + k0 + acg);
                v0 = p[0]; v1 = p[1]; v2 = p[2]; v3 = p[3];
            } else {
                v0 = v1 = v2 = v3 = make_float4(0.f, 0.f, 0.f, 0.f);
            }
            uint4 h0, l0, h1, l1;
            split2(v0.x, v0.y, h0.x, l0.x); split2(v0.z, v0.w, h0.y, l0.y);
            split2(v1.x, v1.y, h0.z, l0.z); split2(v1.z, v1.w, h0.w, l0.w);
            split2(v2.x, v2.y, h1.x, l1.x); split2(v2.z, v2.w, h1.y, l1.y);
            split2(v3.x, v3.y, h1.z, l1.z); split2(v3.z, v3.w, h1.w, l1.w);
            *(uint4*)(sAh + (arow * AST + acg * 2))      = h0;
            *(uint4*)(sAh + (arow * AST + acg * 2 + 16)) = h1;
            *(uint4*)(sAl + (arow * AST + acg * 2))      = l0;
            *(uint4*)(sAl + (arow * AST + acg * 2 + 16)) = l1;
        }
        // ---- B: 4 arrays, straight bf16 copy ----
#pragma unroll
        for (int a4 = 0; a4 < 4; ++a4) {
            const __nv_bfloat16* src = Bsrc[a4] + (size_t)(nt * 64 + brr) * HDIM + k0 + bseg;
            *(uint4*)(sB[a4] + brr * AST + bseg * 2) = *(const uint4*)src;
        }
        __syncthreads();

#pragma unroll
        for (int ks = 0; ks < 2; ++ks) {
            uint32_t ahi[2][4], alo[2][4];
            LDMX4(ahi[0][0], ahi[0][1], ahi[0][2], ahi[0][3], aLdHi + ks * 32);
            LDMX4(ahi[1][0], ahi[1][1], ahi[1][2], ahi[1][3], aLdHi + 16 * AST + ks * 32);
            LDMX4(alo[0][0], alo[0][1], alo[0][2], alo[0][3], aLdLo + ks * 32);
            LDMX4(alo[1][0], alo[1][1], alo[1][2], alo[1][3], aLdLo + 16 * AST + ks * 32);

            uint32_t bh[8], bl[8];
            // w1
            LDMX4(bh[0], bh[1], bh[2], bh[3], bLd[0] + ks * 32);
            LDMX4(bh[4], bh[5], bh[6], bh[7], bLd[0] + 16 * AST + ks * 32);
            LDMX4(bl[0], bl[1], bl[2], bl[3], bLd[1] + ks * 32);
            LDMX4(bl[4], bl[5], bl[6], bl[7], bLd[1] + 16 * AST + ks * 32);
#pragma unroll
            for (int mi = 0; mi < 2; ++mi)
#pragma unroll
                for (int g = 0; g < 4; ++g) {
                    mma_bf16(c1[mi][g], ahi[mi], bh[2 * g], bh[2 * g + 1]);
                    mma_bf16(c1[mi][g], alo[mi], bh[2 * g], bh[2 * g + 1]);
                    mma_bf16(c1[mi][g], ahi[mi], bl[2 * g], bl[2 * g + 1]);
                }
            // w3
            LDMX4(bh[0], bh[1], bh[2], bh[3], bLd[2] + ks * 32);
            LDMX4(bh[4], bh[5], bh[6], bh[7], bLd[2] + 16 * AST + ks * 32);
            LDMX4(bl[0], bl[1], bl[2], bl[3], bLd[3] + ks * 32);
            LDMX4(bl[4], bl[5], bl[6], bl[7], bLd[3] + 16 * AST + ks * 32);
#pragma unroll
            for (int mi = 0; mi < 2; ++mi)
#pragma unroll
                for (int g = 0; g < 4; ++g) {
                    mma_bf16(c3[mi][g], ahi[mi], bh[2 * g], bh[2 * g + 1]);
                    mma_bf16(c3[mi][g], alo[mi], bh[2 * g], bh[2 * g + 1]);
                    mma_bf16(c3[mi][g], ahi[mi], bl[2 * g], bl[2 * g + 1]);
                }
        }
        __syncthreads();
    }

    // ---- epilogue: h = silu(c1)*c3 -> bf16 hi/lo ----
    int trow = lane >> 2, tc2 = (lane & 3) * 2;
#pragma unroll
    for (int mi = 0; mi < 2; ++mi) {
#pragma unroll
        for (int h8 = 0; h8 < 2; ++h8) {
            int row = mt * 128 + wm * 32 + mi * 16 + trow + h8 * 8;
            if (row < M) {
                size_t orow = (size_t)(base + row) * IDIM + nt * 64 + wn * 32;
#pragma unroll
                for (int g = 0; g < 4; ++g) {
                    float f1a = c1[mi][g][h8 * 2 + 0], f1b = c1[mi][g][h8 * 2 + 1];
                    float f3a = c3[mi][g][h8 * 2 + 0], f3b = c3[mi][g][h8 * 2 + 1];
                    float ha = f1a / (1.f + expf(-f1a)) * f3a;
                    float hb = f1b / (1.f + expf(-f1b)) * f3b;
                    uint32_t hi, lo; split2(ha, hb, hi, lo);
                    *(uint32_t*)(g_h_hi + orow + g * 8 + tc2) = hi;
                    *(uint32_t*)(g_h_lo + orow + g * 8 + tc2) = lo;
                }
            }
        }
    }
}

// -------- GEMM2: y = (h @ w2') * wt -> slot scatter --------
__global__ void __launch_bounds__(256, 2)
k_gemm2_mma() {
    __shared__ __align__(16) unsigned char sAh[128 * AST];
    __shared__ __align__(16) unsigned char sAl[128 * AST];
    __shared__ __align__(16) unsigned char sB[2][64 * AST];  // w2 hi, lo

    int e = blockIdx.z, mt = blockIdx.y, nt = blockIdx.x;
    int M = g_counts[e];
    if (mt * 128 >= M) return;
    int base = g_offsets[e];
    int tid = threadIdx.x;

    const __nv_bfloat16* Bh = g_w2t_hi + (size_t)e * HDIM * IDIM;
    const __nv_bfloat16* Bl = g_w2t_lo + (size_t)e * HDIM * IDIM;

    int arow = tid >> 1;
    int acg  = (tid & 1) * 16;
    int agr  = mt * 128 + arow;
    bool aval = agr < M;
    size_t aGbase = (size_t)(base + agr) * IDIM + acg;

    int brr  = tid >> 2;
    int bseg = (tid & 3) * 8;

    int wid = tid >> 5, lane = tid & 31;
    int wm = wid >> 1, wn = wid & 1;
    uint32_t aLdHi = smem_u32(sAh) + (uint32_t)((wm * 32 + (lane & 15)) * AST + (lane >> 4) * 16);
    uint32_t aLdLo = smem_u32(sAl) + (uint32_t)((wm * 32 + (lane & 15)) * AST + (lane >> 4) * 16);
    int n_l = (lane & 7) + ((lane >> 4) << 3);
    uint32_t bOff = (uint32_t)((wn * 32 + n_l) * AST + ((lane >> 3) & 1) * 16);
    uint32_t bLdH = smem_u32(sB[0]) + bOff;
    uint32_t bLdL = smem_u32(sB[1]) + bOff;

    float c[2][4][4];
#pragma unroll
    for (int i = 0; i < 2; ++i)
#pragma unroll
        for (int g = 0; g < 4; ++g)
#pragma unroll
            for (int r = 0; r < 4; ++r) c[i][g][r] = 0.f;

    for (int cch = 0; cch < IDIM / 32; ++cch) {
        int k0 = cch * 32;
        {
            uint4 vh0 = make_uint4(0, 0, 0, 0), vh1 = vh0, vl0 = vh0, vl1 = vh0;
            if (aval) {
                const uint4* ph = (const uint4*)(g_h_hi + aGbase + k0);
                const uint4* pl = (const uint4*)(g_h_lo + aGbase + k0);
                vh0 = ph[0]; vh1 = ph[1];
                vl0 = pl[0]; vl1 = pl[1];
            }
            *(uint4*)(sAh + (arow * AST + acg * 2))      = vh0;
            *(uint4*)(sAh + (arow * AST + acg * 2 + 16)) = vh1;
            *(uint4*)(sAl + (arow * AST + acg * 2))      = vl0;
            *(uint4*)(sAl + (arow * AST + acg * 2 + 16)) = vl1;
        }
        {
            size_t gsrc = (size_t)(nt * 64 + brr) * IDIM + k0 + bseg;
            *(uint4*)(sB[0] + brr * AST + bseg * 2) = *(const uint4*)(Bh + gsrc);
            *(uint4*)(sB[1] + brr * AST + bseg * 2) = *(const uint4*)(Bl + gsrc);
        }
        __syncthreads();

#pragma unroll
        for (int ks = 0; ks < 2; ++ks) {
            uint32_t ahi[2][4], alo[2][4];
            LDMX4(ahi[0][0], ahi[0][1], ahi[0][2], ahi[0][3], aLdHi + ks * 32);
            LDMX4(ahi[1][0], ahi[1][1], ahi[1][2], ahi[1][3], aLdHi + 16 * AST + ks * 32);
            LDMX4(alo[0][0], alo[0][1], alo[0][2], alo[0][3], aLdLo + ks * 32);
            LDMX4(alo[1][0], alo[1][1], alo[1][2], alo[1][3], aLdLo + 16 * AST + ks * 32);
            uint32_t bh[8], bl[8];
            LDMX4(bh[0], bh[1], bh[2], bh[3], bLdH + ks * 32);
            LDMX4(bh[4], bh[5], bh[6], bh[7], bLdH + 16 * AST + ks * 32);
            LDMX4(bl[0], bl[1], bl[2], bl[3], bLdL + ks * 32);
            LDMX4(bl[4], bl[5], bl[6], bl[7], bLdL + 16 * AST + ks * 32);
#pragma unroll
            for (int mi = 0; mi < 2; ++mi)
#pragma unroll
                for (int g = 0; g < 4; ++g) {
                    mma_bf16(c[mi][g], ahi[mi], bh[2 * g], bh[2 * g + 1]);
                    mma_bf16(c[mi][g], alo[mi], bh[2 * g], bh[2 * g + 1]);
                    mma_bf16(c[mi][g], ahi[mi], bl[2 * g], bl[2 * g + 1]);
                }
        }
        __syncthreads();
    }

    // ---- epilogue: scale by routing weight, scatter to slot buffer ----
    int trow = lane >> 2, tc2 = (lane & 3) * 2;
#pragma unroll
    for (int mi = 0; mi < 2; ++mi) {
#pragma unroll
        for (int h8 = 0; h8 < 2; ++h8) {
            int row = mt * 128 + wm * 32 + mi * 16 + trow + h8 * 8;
            if (row < M) {
                int ridx = e * T_TOK + row;
                int tok = g_tok[ridx]; float wt = g_wt[ridx]; int slot = g_slot[ridx];
                float* op = g_slotbuf + (size_t)slot * T_TOK * HDIM
                            + (size_t)tok * HDIM + nt * 64 + wn * 32;
#pragma unroll
                for (int g = 0; g < 4; ++g) {
                    float2 v;
                    v.x = wt * c[mi][g][h8 * 2 + 0];
                    v.y = wt * c[mi][g][h8 * 2 + 1];
                    *(float2*)(op + g * 8 + tc2) = v;
                }
            }
        }
    }
}

// ================= combine =================
__global__ void k_combine(float* __restrict__ out) {
    size_t i = (size_t)blockIdx.x * blockDim.x + threadIdx.x;
    size_t n4 = (size_t)T_TOK * HDIM / 4;
    if (i >= n4) return;
    const float4* s0 = (const float4*)g_slotbuf;
    const float4* s1 = (const float4*)(g_slotbuf + (size_t)T_TOK * HDIM);
    float4 a = s0[i], b = s1[i];
    float4 r;
    r.x = a.x + b.x; r.y = a.y + b.y; r.z = a.z + b.z; r.w = a.w + b.w;
    ((float4*)out)[i] = r;
}

// ================= launcher =================
extern "C" void kernel_launch(void* const* d_in, const int* in_sizes, int n_in,
                              void* d_out, int out_size) {
    const float* x  = (const float*)d_in[0];
    const float* gw = (const float*)d_in[1];
    const float* gb = (const float*)d_in[2];
    const float* w1 = (const float*)d_in[3];
    const float* w3 = (const float*)d_in[4];
    const float* w2 = (const float*)d_in[5];
    float* out = (float*)d_out;

    // split+transpose weights: w1/w3 [H,I]->[I,H], w2 [I,H]->[H,I]
    {
        __nv_bfloat16 *d1h, *d1l, *d3h, *d3l, *d2h, *d2l;
        cudaGetSymbolAddress((void**)&d1h, g_w1t_hi);
        cudaGetSymbolAddress((void**)&d1l, g_w1t_lo);
        cudaGetSymbolAddress((void**)&d3h, g_w3t_hi);
        cudaGetSymbolAddress((void**)&d3l, g_w3t_lo);
        cudaGetSymbolAddress((void**)&d2h, g_w2t_hi);
        cudaGetSymbolAddress((void**)&d2l, g_w2t_lo);
        dim3 t1(IDIM / 32, HDIM / 64, NEXP);
        k_split_transpose<<<t1, 256>>>(w1, d1h, d1l, HDIM, IDIM);
        k_split_transpose<<<t1, 256>>>(w3, d3h, d3l, HDIM, IDIM);
        dim3 t2(HDIM / 32, IDIM / 64, NEXP);
        k_split_transpose<<<t2, 256>>>(w2, d2h, d2l, IDIM, HDIM);
    }

    k_zero_counts<<<1, 32>>>();
    k_gate<<<(T_TOK * 32 + 255) / 256, 256>>>(x, gw, gb);
    k_offsets<<<1, 32>>>();

    dim3 g1(IDIM / 64, T_TOK / 128, NEXP);   // (32, 16, 8)
    k_gemm1_mma<<<g1, 256>>>(x);

    dim3 g2(HDIM / 64, T_TOK / 128, NEXP);   // (16, 16, 8)
    k_gemm2_mma<<<g2, 256>>>();

    size_t n4 = (size_t)T_TOK * HDIM / 4;
    k_combine<<<(unsigned)((n4 + 255) / 256), 256>>>(out);
}

// round 6
// speedup vs baseline: 2.3754x; 1.1011x over previous
#include <cuda_runtime.h>
#include <cuda_bf16.h>
#include <cstdint>
#include <math.h>

// dims
#define T_TOK 2048
#define HDIM  1024
#define IDIM  2048
#define NEXP  8

// ================= device scratch =================
__device__ int   g_counts[NEXP];
__device__ int   g_offsets[NEXP];
__device__ int   g_tok [NEXP * T_TOK];
__device__ float g_wt  [NEXP * T_TOK];
__device__ int   g_slot[NEXP * T_TOK];

// transposed split weights: w1t/w3t: [E][I][H] K-major ; w2t: [E][H][I]
__device__ __nv_bfloat16 g_w1t_hi[(size_t)NEXP * IDIM * HDIM];
__device__ __nv_bfloat16 g_w1t_lo[(size_t)NEXP * IDIM * HDIM];
__device__ __nv_bfloat16 g_w3t_hi[(size_t)NEXP * IDIM * HDIM];
__device__ __nv_bfloat16 g_w3t_lo[(size_t)NEXP * IDIM * HDIM];
__device__ __nv_bfloat16 g_w2t_hi[(size_t)NEXP * HDIM * IDIM];
__device__ __nv_bfloat16 g_w2t_lo[(size_t)NEXP * HDIM * IDIM];

// intermediate h (packed routed rows), pre-split to bf16 hi/lo
__device__ __nv_bfloat16 g_h_hi[(size_t)2 * T_TOK * IDIM];
__device__ __nv_bfloat16 g_h_lo[(size_t)2 * T_TOK * IDIM];
__device__ float g_slotbuf[(size_t)2 * T_TOK * HDIM];

// ================= helpers =================
__device__ __forceinline__ uint32_t smem_u32(const void* p) {
    uint32_t a;
    asm("{ .reg .u64 t; cvta.to.shared.u64 t, %1; cvt.u32.u64 %0, t; }" : "=r"(a) : "l"(p));
    return a;
}

#define LDMX4(r0, r1, r2, r3, addr)                                              \
    asm volatile("ldmatrix.sync.aligned.m8n8.x4.shared.b16 {%0,%1,%2,%3}, [%4];" \
                 : "=r"(r0), "=r"(r1), "=r"(r2), "=r"(r3) : "r"(addr))

#define CP16(dst, src) \
    asm volatile("cp.async.cg.shared.global [%0], [%1], 16;" :: "r"(dst), "l"(src))
#define CP16Z(dst, src, sz) \
    asm volatile("cp.async.cg.shared.global [%0], [%1], 16, %2;" :: "r"(dst), "l"(src), "r"(sz))
#define CP_COMMIT() asm volatile("cp.async.commit_group;" ::: "memory")
#define CP_WAIT0()  asm volatile("cp.async.wait_group 0;" ::: "memory")

__device__ __forceinline__ void mma_bf16(float* d, const uint32_t* a, uint32_t b0, uint32_t b1) {
    asm volatile(
        "mma.sync.aligned.m16n8k16.row.col.f32.bf16.bf16.f32 "
        "{%0,%1,%2,%3}, {%4,%5,%6,%7}, {%8,%9}, {%0,%1,%2,%3};"
        : "+f"(d[0]), "+f"(d[1]), "+f"(d[2]), "+f"(d[3])
        : "r"(a[0]), "r"(a[1]), "r"(a[2]), "r"(a[3]), "r"(b0), "r"(b1));
}

__device__ __forceinline__ void split2(float a, float b, uint32_t& hi, uint32_t& lo) {
    __nv_bfloat16 ha = __float2bfloat16_rn(a), hb = __float2bfloat16_rn(b);
    float ra = a - __bfloat162float(ha), rb = b - __bfloat162float(hb);
    __nv_bfloat162 hp; hp.x = ha; hp.y = hb;
    __nv_bfloat162 lp; lp.x = __float2bfloat16_rn(ra); lp.y = __float2bfloat16_rn(rb);
    hi = *(uint32_t*)&hp; lo = *(uint32_t*)&lp;
}

// ================= gating =================
__global__ void k_zero_counts() { if (threadIdx.x < NEXP) g_counts[threadIdx.x] = 0; }

__global__ void k_gate(const float* __restrict__ x, const float* __restrict__ gw,
                       const float* __restrict__ gb) {
    int warp = (blockIdx.x * blockDim.x + threadIdx.x) >> 5;
    int lane = threadIdx.x & 31;
    if (warp >= T_TOK) return;
    const float* xr = x + (size_t)warp * HDIM;
    float acc[NEXP];
#pragma unroll
    for (int e = 0; e < NEXP; ++e) acc[e] = 0.f;
    for (int h = lane; h < HDIM; h += 32) {
        float xv = xr[h];
        const float4* g4 = (const float4*)(gw + (size_t)h * NEXP);
        float4 a = g4[0], b = g4[1];
        acc[0] += xv * a.x; acc[1] += xv * a.y; acc[2] += xv * a.z; acc[3] += xv * a.w;
        acc[4] += xv * b.x; acc[5] += xv * b.y; acc[6] += xv * b.z; acc[7] += xv * b.w;
    }
#pragma unroll
    for (int o = 16; o > 0; o >>= 1)
#pragma unroll
        for (int e = 0; e < NEXP; ++e) acc[e] += __shfl_xor_sync(0xffffffffu, acc[e], o);
    if (lane == 0) {
        float l[NEXP]; float m = -1e30f;
#pragma unroll
        for (int e = 0; e < NEXP; ++e) { l[e] = acc[e] + gb[e]; m = fmaxf(m, l[e]); }
        float p[NEXP];
#pragma unroll
        for (int e = 0; e < NEXP; ++e) p[e] = expf(l[e] - m);
        int i0 = 0;
#pragma unroll
        for (int e = 1; e < NEXP; ++e) if (p[e] > p[i0]) i0 = e;
        int i1 = (i0 == 0) ? 1 : 0;
#pragma unroll
        for (int e = 0; e < NEXP; ++e) if (e != i0 && p[e] > p[i1]) i1 = e;
        float s = p[i0] + p[i1];
        int p0 = atomicAdd(&g_counts[i0], 1);
        g_tok[i0 * T_TOK + p0] = warp; g_wt[i0 * T_TOK + p0] = p[i0] / s; g_slot[i0 * T_TOK + p0] = 0;
        int p1 = atomicAdd(&g_counts[i1], 1);
        g_tok[i1 * T_TOK + p1] = warp; g_wt[i1 * T_TOK + p1] = p[i1] / s; g_slot[i1 * T_TOK + p1] = 1;
    }
}

__global__ void k_offsets() {
    if (threadIdx.x == 0) {
        int off = 0;
        for (int e = 0; e < NEXP; ++e) { g_offsets[e] = off; off += g_counts[e]; }
    }
}

// ========== fused split+transpose for all 3 weights ==========
// z in [0,24): widx = z>>3 (0:w1, 1:w3, 2:w2), e = z&7
__global__ void k_split_transpose_all(const float* __restrict__ w1,
                                      const float* __restrict__ w3,
                                      const float* __restrict__ w2) {
    __shared__ float tile[64][33];
    int z = blockIdx.z;
    int widx = z >> 3, e = z & 7;

    const float* src; __nv_bfloat16 *dhi, *dlo;
    int K, N, bx, by;
    if (widx == 0) {
        src = w1; dhi = g_w1t_hi; dlo = g_w1t_lo; K = HDIM; N = IDIM;
        bx = blockIdx.x; by = blockIdx.y;
    } else if (widx == 1) {
        src = w3; dhi = g_w3t_hi; dlo = g_w3t_lo; K = HDIM; N = IDIM;
        bx = blockIdx.x; by = blockIdx.y;
    } else {
        src = w2; dhi = g_w2t_hi; dlo = g_w2t_lo; K = IDIM; N = HDIM;
        int flat = blockIdx.y * 64 + blockIdx.x;   // 0..1023
        bx = flat & 31; by = flat >> 5;            // x: N/32=32, y: K/64=32
    }

    const float* s = src + (size_t)e * K * N;
    __nv_bfloat16* oh = dhi + (size_t)e * K * N;
    __nv_bfloat16* ol = dlo + (size_t)e * K * N;
    int k0 = by * 64, n0 = bx * 32;
    int tx = threadIdx.x & 31, ty = threadIdx.x >> 5;
#pragma unroll
    for (int kk = ty; kk < 64; kk += 8)
        tile[kk][tx] = s[(size_t)(k0 + kk) * N + n0 + tx];
    __syncthreads();
#pragma unroll
    for (int r = ty; r < 32; r += 8) {
        float v0 = tile[2 * tx][r], v1 = tile[2 * tx + 1][r];
        uint32_t hi, lo; split2(v0, v1, hi, lo);
        size_t base = (size_t)(n0 + r) * K + k0;
        ((uint32_t*)(oh + base))[tx] = hi;
        ((uint32_t*)(ol + base))[tx] = lo;
    }
}

// ================= mma.sync GEMM tiling =================
// CTA tile: 128(M) x 64(N), BK=32. 8 warps as 4(M) x 2(N); warp tile 32x32.
// smem rows padded to 80B; 2-stage double buffer in dynamic smem.
#define AST 80
#define ABUF 10240            // 128*AST
#define BBUF 5120             // 64*AST

// GEMM1 stage layout: [Ahi | Alo | B0..B3] = 40960 B per stage
#define G1_STAGE 40960
#define G1_TOTAL (2 * G1_STAGE + 512)
// GEMM2 stage layout: [Ahi | Alo | B0 B1] = 30720 B per stage
#define G2_STAGE 30720
#define G2_TOTAL (2 * G2_STAGE)

// -------- GEMM1: c1 = Xg @ w1', c3 = Xg @ w3' ; h = silu(c1)*c3 --------
__global__ void __launch_bounds__(256, 2)
k_gemm1_mma(const float* __restrict__ x) {
    extern __shared__ __align__(16) unsigned char smem[];
    int e = blockIdx.z, mt = blockIdx.y, nt = blockIdx.x;
    int M = g_counts[e];
    if (mt * 128 >= M) return;
    int base = g_offsets[e];
    int tid = threadIdx.x;
    uint32_t sb = smem_u32(smem);

    int* toks = (int*)(smem + 2 * G1_STAGE);
    if (tid < 128) {
        int r = mt * 128 + tid;
        toks[tid] = (r < M) ? g_tok[e * T_TOK + r] : -1;
    }
    __syncthreads();

    const __nv_bfloat16* Bsrc[4];
    Bsrc[0] = g_w1t_hi + (size_t)e * IDIM * HDIM;
    Bsrc[1] = g_w1t_lo + (size_t)e * IDIM * HDIM;
    Bsrc[2] = g_w3t_hi + (size_t)e * IDIM * HDIM;
    Bsrc[3] = g_w3t_lo + (size_t)e * IDIM * HDIM;

    // loader indices
    int arow = tid >> 1;               // 0..127
    int acg  = (tid & 1) * 16;         // fp32 col group of 16
    int tokA = toks[arow];
    const float* xrow = (tokA >= 0) ? (x + (size_t)tokA * HDIM) : (const float*)0;
    uint32_t aOff = (uint32_t)(arow * AST + acg * 2);

    int brr  = tid >> 2;               // 0..63
    int bseg = (tid & 3) * 8;          // 8 bf16 = 16B
    uint32_t bDstOff = (uint32_t)(brr * AST + bseg * 2);

    // mma indices
    int wid = tid >> 5, lane = tid & 31;
    int wm = wid >> 1, wn = wid & 1;
    uint32_t aFragOff = (uint32_t)((wm * 32 + (lane & 15)) * AST + (lane >> 4) * 16);
    int n_l = (lane & 7) + ((lane >> 4) << 3);
    uint32_t bFragOff = (uint32_t)((wn * 32 + n_l) * AST + ((lane >> 3) & 1) * 16);

    float c1[2][4][4], c3[2][4][4];
#pragma unroll
    for (int i = 0; i < 2; ++i)
#pragma unroll
        for (int g = 0; g < 4; ++g)
#pragma unroll
            for (int r = 0; r < 4; ++r) { c1[i][g][r] = 0.f; c3[i][g][r] = 0.f; }

    float4 v0, v1, v2, v3;
    // ---- prologue: A(0) regs, B(0) cp.async -> stage 0 ----
    if (xrow) {
        const float4* p = (const float4*)(xrow + 0 + acg);
        v0 = p[0]; v1 = p[1]; v2 = p[2]; v3 = p[3];
    } else v0 = v1 = v2 = v3 = make_float4(0.f, 0.f, 0.f, 0.f);
#pragma unroll
    for (int a4 = 0; a4 < 4; ++a4) {
        const __nv_bfloat16* src = Bsrc[a4] + (size_t)(nt * 64 + brr) * HDIM + 0 + bseg;
        CP16(sb + 2 * ABUF + a4 * BBUF + bDstOff, src);
    }
    CP_COMMIT();

    const int NC = HDIM / 32;
    for (int c = 0; c < NC; ++c) {
        uint32_t stg = (uint32_t)(c & 1) * G1_STAGE;
        // ---- store A(c) from regs (split) into this stage ----
        {
            uint4 h0, l0, h1, l1;
            split2(v0.x, v0.y, h0.x, l0.x); split2(v0.z, v0.w, h0.y, l0.y);
            split2(v1.x, v1.y, h0.z, l0.z); split2(v1.z, v1.w, h0.w, l0.w);
            split2(v2.x, v2.y, h1.x, l1.x); split2(v2.z, v2.w, h1.y, l1.y);
            split2(v3.x, v3.y, h1.z, l1.z); split2(v3.z, v3.w, h1.w, l1.w);
            unsigned char* st = smem + stg;
            *(uint4*)(st + aOff)              = h0;
            *(uint4*)(st + aOff + 16)         = h1;
            *(uint4*)(st + ABUF + aOff)       = l0;
            *(uint4*)(st + ABUF + aOff + 16)  = l1;
        }
        CP_WAIT0();
        __syncthreads();
        // ---- prefetch next stage (after barrier: safe) ----
        if (c + 1 < NC) {
            int k1 = (c + 1) * 32;
            if (xrow) {
                const float4* p = (const float4*)(xrow + k1 + acg);
                v0 = p[0]; v1 = p[1]; v2 = p[2]; v3 = p[3];
            }
            uint32_t nstg = sb + (uint32_t)((c + 1) & 1) * G1_STAGE + 2 * ABUF;
#pragma unroll
            for (int a4 = 0; a4 < 4; ++a4) {
                const __nv_bfloat16* src = Bsrc[a4] + (size_t)(nt * 64 + brr) * HDIM + k1 + bseg;
                CP16(nstg + a4 * BBUF + bDstOff, src);
            }
            CP_COMMIT();
        }
        // ---- mma on stage c ----
        uint32_t aLdHi = sb + stg + aFragOff;
        uint32_t aLdLo = sb + stg + ABUF + aFragOff;
        uint32_t bBase = sb + stg + 2 * ABUF;
#pragma unroll
        for (int ks = 0; ks < 2; ++ks) {
            uint32_t ahi[2][4], alo[2][4];
            LDMX4(ahi[0][0], ahi[0][1], ahi[0][2], ahi[0][3], aLdHi + ks * 32);
            LDMX4(ahi[1][0], ahi[1][1], ahi[1][2], ahi[1][3], aLdHi + 16 * AST + ks * 32);
            LDMX4(alo[0][0], alo[0][1], alo[0][2], alo[0][3], aLdLo + ks * 32);
            LDMX4(alo[1][0], alo[1][1], alo[1][2], alo[1][3], aLdLo + 16 * AST + ks * 32);

            uint32_t bh[8], bl[8];
            // w1
            LDMX4(bh[0], bh[1], bh[2], bh[3], bBase + 0 * BBUF + bFragOff + ks * 32);
            LDMX4(bh[4], bh[5], bh[6], bh[7], bBase + 0 * BBUF + bFragOff + 16 * AST + ks * 32);
            LDMX4(bl[0], bl[1], bl[2], bl[3], bBase + 1 * BBUF + bFragOff + ks * 32);
            LDMX4(bl[4], bl[5], bl[6], bl[7], bBase + 1 * BBUF + bFragOff + 16 * AST + ks * 32);
#pragma unroll
            for (int mi = 0; mi < 2; ++mi)
#pragma unroll
                for (int g = 0; g < 4; ++g) {
                    mma_bf16(c1[mi][g], ahi[mi], bh[2 * g], bh[2 * g + 1]);
                    mma_bf16(c1[mi][g], alo[mi], bh[2 * g], bh[2 * g + 1]);
                    mma_bf16(c1[mi][g], ahi[mi], bl[2 * g], bl[2 * g + 1]);
                }
            // w3
            LDMX4(bh[0], bh[1], bh[2], bh[3], bBase + 2 * BBUF + bFragOff + ks * 32);
            LDMX4(bh[4], bh[5], bh[6], bh[7], bBase + 2 * BBUF + bFragOff + 16 * AST + ks * 32);
            LDMX4(bl[0], bl[1], bl[2], bl[3], bBase + 3 * BBUF + bFragOff + ks * 32);
            LDMX4(bl[4], bl[5], bl[6], bl[7], bBase + 3 * BBUF + bFragOff + 16 * AST + ks * 32);
#pragma unroll
            for (int mi = 0; mi < 2; ++mi)
#pragma unroll
                for (int g = 0; g < 4; ++g) {
                    mma_bf16(c3[mi][g], ahi[mi], bh[2 * g], bh[2 * g + 1]);
                    mma_bf16(c3[mi][g], alo[mi], bh[2 * g], bh[2 * g + 1]);
                    mma_bf16(c3[mi][g], ahi[mi], bl[2 * g], bl[2 * g + 1]);
                }
        }
    }

    // ---- epilogue: h = silu(c1)*c3 -> bf16 hi/lo ----
    int trow = lane >> 2, tc2 = (lane & 3) * 2;
#pragma unroll
    for (int mi = 0; mi < 2; ++mi) {
#pragma unroll
        for (int h8 = 0; h8 < 2; ++h8) {
            int row = mt * 128 + wm * 32 + mi * 16 + trow + h8 * 8;
            if (row < M) {
                size_t orow = (size_t)(base + row) * IDIM + nt * 64 + wn * 32;
#pragma unroll
                for (int g = 0; g < 4; ++g) {
                    float f1a = c1[mi][g][h8 * 2 + 0], f1b = c1[mi][g][h8 * 2 + 1];
                    float f3a = c3[mi][g][h8 * 2 + 0], f3b = c3[mi][g][h8 * 2 + 1];
                    float ha = f1a / (1.f + expf(-f1a)) * f3a;
                    float hb = f1b / (1.f + expf(-f1b)) * f3b;
                    uint32_t hi, lo; split2(ha, hb, hi, lo);
                    *(uint32_t*)(g_h_hi + orow + g * 8 + tc2) = hi;
                    *(uint32_t*)(g_h_lo + orow + g * 8 + tc2) = lo;
                }
            }
        }
    }
}

// -------- GEMM2: y = (h @ w2') * wt -> slot scatter --------
__global__ void __launch_bounds__(256, 2)
k_gemm2_mma() {
    extern __shared__ __align__(16) unsigned char smem[];
    int e = blockIdx.z, mt = blockIdx.y, nt = blockIdx.x;
    int M = g_counts[e];
    if (mt * 128 >= M) return;
    int base = g_offsets[e];
    int tid = threadIdx.x;
    uint32_t sb = smem_u32(smem);

    const __nv_bfloat16* Bh = g_w2t_hi + (size_t)e * HDIM * IDIM;
    const __nv_bfloat16* Bl = g_w2t_lo + (size_t)e * HDIM * IDIM;

    int arow = tid >> 1;
    int acg  = (tid & 1) * 16;
    int agr  = mt * 128 + arow;
    uint32_t aSz = (agr < M) ? 16u : 0u;
    size_t aGbase = (size_t)(base + agr) * IDIM + acg;
    uint32_t aOff = (uint32_t)(arow * AST + acg * 2);

    int brr  = tid >> 2;
    int bseg = (tid & 3) * 8;
    uint32_t bDstOff = (uint32_t)(brr * AST + bseg * 2);

    int wid = tid >> 5, lane = tid & 31;
    int wm = wid >> 1, wn = wid & 1;
    uint32_t aFragOff = (uint32_t)((wm * 32 + (lane & 15)) * AST + (lane >> 4) * 16);
    int n_l = (lane & 7) + ((lane >> 4) << 3);
    uint32_t bFragOff = (uint32_t)((wn * 32 + n_l) * AST + ((lane >> 3) & 1) * 16);

    float c[2][4][4];
#pragma unroll
    for (int i = 0; i < 2; ++i)
#pragma unroll
        for (int g = 0; g < 4; ++g)
#pragma unroll
            for (int r = 0; r < 4; ++r) c[i][g][r] = 0.f;

    // ---- prologue: stage 0 ----
    {
        uint32_t st = sb;
        CP16Z(st + aOff,              g_h_hi + aGbase,     aSz);
        CP16Z(st + aOff + 16,         g_h_hi + aGbase + 8, aSz);
        CP16Z(st + ABUF + aOff,       g_h_lo + aGbase,     aSz);
        CP16Z(st + ABUF + aOff + 16,  g_h_lo + aGbase + 8, aSz);
        size_t gsrc = (size_t)(nt * 64 + brr) * IDIM + 0 + bseg;
        CP16(st + 2 * ABUF + bDstOff,        Bh + gsrc);
        CP16(st + 2 * ABUF + BBUF + bDstOff, Bl + gsrc);
    }
    CP_COMMIT();

    const int NC = IDIM / 32;
    for (int cc = 0; cc < NC; ++cc) {
        uint32_t stg = (uint32_t)(cc & 1) * G2_STAGE;
        CP_WAIT0();
        __syncthreads();
        if (cc + 1 < NC) {
            int k1 = (cc + 1) * 32;
            uint32_t st = sb + (uint32_t)((cc + 1) & 1) * G2_STAGE;
            CP16Z(st + aOff,              g_h_hi + aGbase + k1,     aSz);
            CP16Z(st + aOff + 16,         g_h_hi + aGbase + k1 + 8, aSz);
            CP16Z(st + ABUF + aOff,       g_h_lo + aGbase + k1,     aSz);
            CP16Z(st + ABUF + aOff + 16,  g_h_lo + aGbase + k1 + 8, aSz);
            size_t gsrc = (size_t)(nt * 64 + brr) * IDIM + k1 + bseg;
            CP16(st + 2 * ABUF + bDstOff,        Bh + gsrc);
            CP16(st + 2 * ABUF + BBUF + bDstOff, Bl + gsrc);
            CP_COMMIT();
        }
        uint32_t aLdHi = sb + stg + aFragOff;
        uint32_t aLdLo = sb + stg + ABUF + aFragOff;
        uint32_t bLdH  = sb + stg + 2 * ABUF + bFragOff;
        uint32_t bLdL  = sb + stg + 2 * ABUF + BBUF + bFragOff;
#pragma unroll
        for (int ks = 0; ks < 2; ++ks) {
            uint32_t ahi[2][4], alo[2][4];
            LDMX4(ahi[0][0], ahi[0][1], ahi[0][2], ahi[0][3], aLdHi + ks * 32);
            LDMX4(ahi[1][0], ahi[1][1], ahi[1][2], ahi[1][3], aLdHi + 16 * AST + ks * 32);
            LDMX4(alo[0][0], alo[0][1], alo[0][2], alo[0][3], aLdLo + ks * 32);
            LDMX4(alo[1][0], alo[1][1], alo[1][2], alo[1][3], aLdLo + 16 * AST + ks * 32);
            uint32_t bh[8], bl[8];
            LDMX4(bh[0], bh[1], bh[2], bh[3], bLdH + ks * 32);
            LDMX4(bh[4], bh[5], bh[6], bh[7], bLdH + 16 * AST + ks * 32);
            LDMX4(bl[0], bl[1], bl[2], bl[3], bLdL + ks * 32);
            LDMX4(bl[4], bl[5], bl[6], bl[7], bLdL + 16 * AST + ks * 32);
#pragma unroll
            for (int mi = 0; mi < 2; ++mi)
#pragma unroll
                for (int g = 0; g < 4; ++g) {
                    mma_bf16(c[mi][g], ahi[mi], bh[2 * g], bh[2 * g + 1]);
                    mma_bf16(c[mi][g], alo[mi], bh[2 * g], bh[2 * g + 1]);
                    mma_bf16(c[mi][g], ahi[mi], bl[2 * g], bl[2 * g + 1]);
                }
        }
    }

    // ---- epilogue: scale by routing weight, scatter to slot buffer ----
    int trow = lane >> 2, tc2 = (lane & 3) * 2;
#pragma unroll
    for (int mi = 0; mi < 2; ++mi) {
#pragma unroll
        for (int h8 = 0; h8 < 2; ++h8) {
            int row = mt * 128 + wm * 32 + mi * 16 + trow + h8 * 8;
            if (row < M) {
                int ridx = e * T_TOK + row;
                int tok = g_tok[ridx]; float wt = g_wt[ridx]; int slot = g_slot[ridx];
                float* op = g_slotbuf + (size_t)slot * T_TOK * HDIM
                            + (size_t)tok * HDIM + nt * 64 + wn * 32;
#pragma unroll
                for (int g = 0; g < 4; ++g) {
                    float2 v;
                    v.x = wt * c[mi][g][h8 * 2 + 0];
                    v.y = wt * c[mi][g][h8 * 2 + 1];
                    *(float2*)(op + g * 8 + tc2) = v;
                }
            }
        }
    }
}

// ================= combine =================
__global__ void k_combine(float* __restrict__ out) {
    size_t i = (size_t)blockIdx.x * blockDim.x + threadIdx.x;
    size_t n4 = (size_t)T_TOK * HDIM / 4;
    if (i >= n4) return;
    const float4* s0 = (const float4*)g_slotbuf;
    const float4* s1 = (const float4*)(g_slotbuf + (size_t)T_TOK * HDIM);
    float4 a = s0[i], b = s1[i];
    float4 r;
    r.x = a.x + b.x; r.y = a.y + b.y; r.z = a.z + b.z; r.w = a.w + b.w;
    ((float4*)out)[i] = r;
}

// ================= launcher =================
extern "C" void kernel_launch(void* const* d_in, const int* in_sizes, int n_in,
                              void* d_out, int out_size) {
    const float* x  = (const float*)d_in[0];
    const float* gw = (const float*)d_in[1];
    const float* gb = (const float*)d_in[2];
    const float* w1 = (const float*)d_in[3];
    const float* w3 = (const float*)d_in[4];
    const float* w2 = (const float*)d_in[5];
    float* out = (float*)d_out;

    static int configured = 0;
    if (!configured) {
        cudaFuncSetAttribute(k_gemm1_mma, cudaFuncAttributeMaxDynamicSharedMemorySize, G1_TOTAL);
        cudaFuncSetAttribute(k_gemm2_mma, cudaFuncAttributeMaxDynamicSharedMemorySize, G2_TOTAL);
        configured = 1;
    }

    dim3 tg(64, 16, 24);
    k_split_transpose_all<<<tg, 256>>>(w1, w3, w2);

    k_zero_counts<<<1, 32>>>();
    k_gate<<<(T_TOK * 32 + 255) / 256, 256>>>(x, gw, gb);
    k_offsets<<<1, 32>>>();

    dim3 g1(IDIM / 64, T_TOK / 128, NEXP);   // (32, 16, 8)
    k_gemm1_mma<<<g1, 256, G1_TOTAL>>>(x);

    dim3 g2(HDIM / 64, T_TOK / 128, NEXP);   // (16, 16, 8)
    k_gemm2_mma<<<g2, 256, G2_TOTAL>>>();

    size_t n4 = (size_t)T_TOK * HDIM / 4;
    k_combine<<<(unsigned)((n4 + 255) / 256), 256>>>(out);
}

// round 7
// speedup vs baseline: 2.5114x; 1.0572x over previous
#include <cuda_runtime.h>
#include <cuda_bf16.h>
#include <cstdint>
#include <math.h>

// dims
#define T_TOK 2048
#define HDIM  1024
#define IDIM  2048
#define NEXP  8

// ================= device scratch =================
__device__ int   g_counts[NEXP];
__device__ int   g_offsets[NEXP];
__device__ int   g_tok [NEXP * T_TOK];
__device__ float g_wt  [NEXP * T_TOK];
__device__ int   g_slot[NEXP * T_TOK];

// intermediate h (packed routed rows), pre-split to bf16 hi/lo
__device__ __nv_bfloat16 g_h_hi[(size_t)2 * T_TOK * IDIM];
__device__ __nv_bfloat16 g_h_lo[(size_t)2 * T_TOK * IDIM];
__device__ float g_slotbuf[(size_t)2 * T_TOK * HDIM];

// ================= helpers =================
__device__ __forceinline__ uint32_t smem_u32(const void* p) {
    uint32_t a;
    asm("{ .reg .u64 t; cvta.to.shared.u64 t, %1; cvt.u32.u64 %0, t; }" : "=r"(a) : "l"(p));
    return a;
}

#define LDMX4(r0, r1, r2, r3, addr)                                              \
    asm volatile("ldmatrix.sync.aligned.m8n8.x4.shared.b16 {%0,%1,%2,%3}, [%4];" \
                 : "=r"(r0), "=r"(r1), "=r"(r2), "=r"(r3) : "r"(addr))

#define LDMX4T(r0, r1, r2, r3, addr)                                                   \
    asm volatile("ldmatrix.sync.aligned.m8n8.x4.trans.shared.b16 {%0,%1,%2,%3}, [%4];" \
                 : "=r"(r0), "=r"(r1), "=r"(r2), "=r"(r3) : "r"(addr))

#define CP16(dst, src) \
    asm volatile("cp.async.cg.shared.global [%0], [%1], 16;" :: "r"(dst), "l"(src))
#define CP16Z(dst, src, sz) \
    asm volatile("cp.async.cg.shared.global [%0], [%1], 16, %2;" :: "r"(dst), "l"(src), "r"(sz))
#define CP_COMMIT() asm volatile("cp.async.commit_group;" ::: "memory")
#define CP_WAIT0()  asm volatile("cp.async.wait_group 0;" ::: "memory")

__device__ __forceinline__ void mma_bf16(float* d, const uint32_t* a, uint32_t b0, uint32_t b1) {
    asm volatile(
        "mma.sync.aligned.m16n8k16.row.col.f32.bf16.bf16.f32 "
        "{%0,%1,%2,%3}, {%4,%5,%6,%7}, {%8,%9}, {%0,%1,%2,%3};"
        : "+f"(d[0]), "+f"(d[1]), "+f"(d[2]), "+f"(d[3])
        : "r"(a[0]), "r"(a[1]), "r"(a[2]), "r"(a[3]), "r"(b0), "r"(b1));
}

__device__ __forceinline__ void split2(float a, float b, uint32_t& hi, uint32_t& lo) {
    __nv_bfloat16 ha = __float2bfloat16_rn(a), hb = __float2bfloat16_rn(b);
    float ra = a - __bfloat162float(ha), rb = b - __bfloat162float(hb);
    __nv_bfloat162 hp; hp.x = ha; hp.y = hb;
    __nv_bfloat162 lp; lp.x = __float2bfloat16_rn(ra); lp.y = __float2bfloat16_rn(rb);
    hi = *(uint32_t*)&hp; lo = *(uint32_t*)&lp;
}

// split a float4 into hi/lo bf16x2 pairs (uint2 each)
__device__ __forceinline__ void split4(const float4& v, uint2& hi, uint2& lo) {
    split2(v.x, v.y, hi.x, lo.x);
    split2(v.z, v.w, hi.y, lo.y);
}

// ================= gating =================
__global__ void k_zero_counts() { if (threadIdx.x < NEXP) g_counts[threadIdx.x] = 0; }

__global__ void k_gate(const float* __restrict__ x, const float* __restrict__ gw,
                       const float* __restrict__ gb) {
    int warp = (blockIdx.x * blockDim.x + threadIdx.x) >> 5;
    int lane = threadIdx.x & 31;
    if (warp >= T_TOK) return;
    const float* xr = x + (size_t)warp * HDIM;
    float acc[NEXP];
#pragma unroll
    for (int e = 0; e < NEXP; ++e) acc[e] = 0.f;
    for (int h = lane; h < HDIM; h += 32) {
        float xv = xr[h];
        const float4* g4 = (const float4*)(gw + (size_t)h * NEXP);
        float4 a = g4[0], b = g4[1];
        acc[0] += xv * a.x; acc[1] += xv * a.y; acc[2] += xv * a.z; acc[3] += xv * a.w;
        acc[4] += xv * b.x; acc[5] += xv * b.y; acc[6] += xv * b.z; acc[7] += xv * b.w;
    }
#pragma unroll
    for (int o = 16; o > 0; o >>= 1)
#pragma unroll
        for (int e = 0; e < NEXP; ++e) acc[e] += __shfl_xor_sync(0xffffffffu, acc[e], o);
    if (lane == 0) {
        float l[NEXP]; float m = -1e30f;
#pragma unroll
        for (int e = 0; e < NEXP; ++e) { l[e] = acc[e] + gb[e]; m = fmaxf(m, l[e]); }
        float p[NEXP];
#pragma unroll
        for (int e = 0; e < NEXP; ++e) p[e] = expf(l[e] - m);
        int i0 = 0;
#pragma unroll
        for (int e = 1; e < NEXP; ++e) if (p[e] > p[i0]) i0 = e;
        int i1 = (i0 == 0) ? 1 : 0;
#pragma unroll
        for (int e = 0; e < NEXP; ++e) if (e != i0 && p[e] > p[i1]) i1 = e;
        float s = p[i0] + p[i1];
        int p0 = atomicAdd(&g_counts[i0], 1);
        g_tok[i0 * T_TOK + p0] = warp; g_wt[i0 * T_TOK + p0] = p[i0] / s; g_slot[i0 * T_TOK + p0] = 0;
        int p1 = atomicAdd(&g_counts[i1], 1);
        g_tok[i1 * T_TOK + p1] = warp; g_wt[i1 * T_TOK + p1] = p[i1] / s; g_slot[i1 * T_TOK + p1] = 1;
    }
}

__global__ void k_offsets() {
    if (threadIdx.x == 0) {
        int off = 0;
        for (int e = 0; e < NEXP; ++e) { g_offsets[e] = off; off += g_counts[e]; }
    }
}

// ================= GEMM tiling =================
// CTA tile: 128(M) x 64(N), BK=32. 8 warps as 4(M) x 2(N); warp tile 32x32.
// A smem: [128 rows][32 bf16 + pad] stride 80.
// B smem: [32 k-rows][64 bf16 + pad] stride 144 (trans-ldmatrix layout).
#define AST 80
#define BST 144
#define G1_A 10240            // 128*80
#define G_B  4608             // 32*144

// GEMM1 stage: Ahi Alo | w1hi w1lo w3hi w3lo
#define G1_STAGE (2 * G1_A + 4 * G_B)   // 38912
#define G1_TOTAL (2 * G1_STAGE + 512)   // 78336
// GEMM2 stage: Ahi Alo | w2hi w2lo
#define G2_STAGE (2 * G1_A + 2 * G_B)   // 29696
#define G2_TOTAL (2 * G2_STAGE)         // 59392

// -------- GEMM1: c1 = Xg @ w1, c3 = Xg @ w3 ; h = silu(c1)*c3 --------
__global__ void __launch_bounds__(256, 1)
k_gemm1_mma(const float* __restrict__ x,
            const float* __restrict__ w1g,
            const float* __restrict__ w3g) {
    extern __shared__ __align__(16) unsigned char smem[];
    int e = blockIdx.z, mt = blockIdx.y, nt = blockIdx.x;
    int M = g_counts[e];
    if (mt * 128 >= M) return;
    int base = g_offsets[e];
    int tid = threadIdx.x;
    uint32_t sb = smem_u32(smem);

    int* toks = (int*)(smem + 2 * G1_STAGE);
    if (tid < 128) {
        int r = mt * 128 + tid;
        toks[tid] = (r < M) ? g_tok[e * T_TOK + r] : -1;
    }
    __syncthreads();

    const float* W1 = w1g + (size_t)e * HDIM * IDIM;   // [H=K, I=N] row-major
    const float* W3 = w3g + (size_t)e * HDIM * IDIM;

    // A loader: 2 threads per row, each 16 fp32
    int arow = tid >> 1;
    int acg  = (tid & 1) * 16;
    int tokA = toks[arow];
    const float* xrow = (tokA >= 0) ? (x + (size_t)tokA * HDIM) : (const float*)0;
    uint32_t aOff = (uint32_t)(arow * AST + acg * 2);

    // B loader: tile 32k x 64n fp32 = 512 float4; thread handles f4 idx tid, tid+256
    int bk0 = tid >> 4,        bc0 = (tid & 15) * 4;
    int bk1 = (tid + 256) >> 4, bc1 = (tid & 15) * 4;   // (tid+256)&15 == tid&15
    uint32_t bO0 = (uint32_t)(bk0 * BST + bc0 * 2);
    uint32_t bO1 = (uint32_t)(bk1 * BST + bc1 * 2);

    // mma indices
    int wid = tid >> 5, lane = tid & 31;
    int wm = wid >> 1, wn = wid & 1;
    uint32_t aFragOff = (uint32_t)((wm * 32 + (lane & 15)) * AST + (lane >> 4) * 16);
    uint32_t bFragOff = (uint32_t)(((lane & 7) + ((lane >> 3) & 1) * 8) * BST
                                   + (wn * 32 + ((lane >> 4) & 1) * 8) * 2);

    float c1[2][4][4], c3[2][4][4];
#pragma unroll
    for (int i = 0; i < 2; ++i)
#pragma unroll
        for (int g = 0; g < 4; ++g)
#pragma unroll
            for (int r = 0; r < 4; ++r) { c1[i][g][r] = 0.f; c3[i][g][r] = 0.f; }

    float4 av0, av1, av2, av3;          // A prefetch
    float4 b1v0, b1v1, b3v0, b3v1;      // B prefetch (w1, w3)

    // ---- prologue: load chunk 0 into regs ----
    if (xrow) {
        const float4* p = (const float4*)(xrow + acg);
        av0 = p[0]; av1 = p[1]; av2 = p[2]; av3 = p[3];
    } else av0 = av1 = av2 = av3 = make_float4(0.f, 0.f, 0.f, 0.f);
    {
        size_t g0 = (size_t)bk0 * IDIM + nt * 64 + bc0;
        size_t g1 = (size_t)bk1 * IDIM + nt * 64 + bc1;
        b1v0 = *(const float4*)(W1 + g0); b1v1 = *(const float4*)(W1 + g1);
        b3v0 = *(const float4*)(W3 + g0); b3v1 = *(const float4*)(W3 + g1);
    }

    const int NC = HDIM / 32;
    for (int c = 0; c < NC; ++c) {
        uint32_t stg = (uint32_t)(c & 1) * G1_STAGE;
        unsigned char* st = smem + stg;
        // ---- STS A (split) ----
        {
            uint2 h0, l0, h1, l1, h2, l2, h3, l3;
            split4(av0, h0, l0); split4(av1, h1, l1);
            split4(av2, h2, l2); split4(av3, h3, l3);
            *(uint4*)(st + aOff)             = make_uint4(h0.x, h0.y, h1.x, h1.y);
            *(uint4*)(st + aOff + 16)        = make_uint4(h2.x, h2.y, h3.x, h3.y);
            *(uint4*)(st + G1_A + aOff)      = make_uint4(l0.x, l0.y, l1.x, l1.y);
            *(uint4*)(st + G1_A + aOff + 16) = make_uint4(l2.x, l2.y, l3.x, l3.y);
        }
        // ---- STS B (split) ----
        {
            unsigned char* b1h = st + 2 * G1_A;
            unsigned char* b1l = b1h + G_B;
            unsigned char* b3h = b1l + G_B;
            unsigned char* b3l = b3h + G_B;
            uint2 h, l;
            split4(b1v0, h, l); *(uint2*)(b1h + bO0) = h; *(uint2*)(b1l + bO0) = l;
            split4(b1v1, h, l); *(uint2*)(b1h + bO1) = h; *(uint2*)(b1l + bO1) = l;
            split4(b3v0, h, l); *(uint2*)(b3h + bO0) = h; *(uint2*)(b3l + bO0) = l;
            split4(b3v1, h, l); *(uint2*)(b3h + bO1) = h; *(uint2*)(b3l + bO1) = l;
        }
        __syncthreads();
        // ---- prefetch next chunk ----
        if (c + 1 < NC) {
            int k1 = (c + 1) * 32;
            if (xrow) {
                const float4* p = (const float4*)(xrow + k1 + acg);
                av0 = p[0]; av1 = p[1]; av2 = p[2]; av3 = p[3];
            }
            size_t g0 = (size_t)(k1 + bk0) * IDIM + nt * 64 + bc0;
            size_t g1 = (size_t)(k1 + bk1) * IDIM + nt * 64 + bc1;
            b1v0 = *(const float4*)(W1 + g0); b1v1 = *(const float4*)(W1 + g1);
            b3v0 = *(const float4*)(W3 + g0); b3v1 = *(const float4*)(W3 + g1);
        }
        // ---- mma on stage c ----
        uint32_t aLdHi = sb + stg + aFragOff;
        uint32_t aLdLo = sb + stg + G1_A + aFragOff;
        uint32_t bB1h  = sb + stg + 2 * G1_A + bFragOff;
        uint32_t bB1l  = bB1h + G_B;
        uint32_t bB3h  = bB1l + G_B;
        uint32_t bB3l  = bB3h + G_B;
#pragma unroll
        for (int ks = 0; ks < 2; ++ks) {
            uint32_t kof = ks * 16 * BST;
            uint32_t ahi[2][4], alo[2][4];
            LDMX4(ahi[0][0], ahi[0][1], ahi[0][2], ahi[0][3], aLdHi + ks * 32);
            LDMX4(ahi[1][0], ahi[1][1], ahi[1][2], ahi[1][3], aLdHi + 16 * AST + ks * 32);
            LDMX4(alo[0][0], alo[0][1], alo[0][2], alo[0][3], aLdLo + ks * 32);
            LDMX4(alo[1][0], alo[1][1], alo[1][2], alo[1][3], aLdLo + 16 * AST + ks * 32);

            uint32_t bh[8], bl[8];
            // w1
            LDMX4T(bh[0], bh[1], bh[2], bh[3], bB1h + kof);
            LDMX4T(bh[4], bh[5], bh[6], bh[7], bB1h + kof + 32);
            LDMX4T(bl[0], bl[1], bl[2], bl[3], bB1l + kof);
            LDMX4T(bl[4], bl[5], bl[6], bl[7], bB1l + kof + 32);
#pragma unroll
            for (int mi = 0; mi < 2; ++mi)
#pragma unroll
                for (int g = 0; g < 4; ++g) {
                    mma_bf16(c1[mi][g], ahi[mi], bh[2 * g], bh[2 * g + 1]);
                    mma_bf16(c1[mi][g], alo[mi], bh[2 * g], bh[2 * g + 1]);
                    mma_bf16(c1[mi][g], ahi[mi], bl[2 * g], bl[2 * g + 1]);
                }
            // w3
            LDMX4T(bh[0], bh[1], bh[2], bh[3], bB3h + kof);
            LDMX4T(bh[4], bh[5], bh[6], bh[7], bB3h + kof + 32);
            LDMX4T(bl[0], bl[1], bl[2], bl[3], bB3l + kof);
            LDMX4T(bl[4], bl[5], bl[6], bl[7], bB3l + kof + 32);
#pragma unroll
            for (int mi = 0; mi < 2; ++mi)
#pragma unroll
                for (int g = 0; g < 4; ++g) {
                    mma_bf16(c3[mi][g], ahi[mi], bh[2 * g], bh[2 * g + 1]);
                    mma_bf16(c3[mi][g], alo[mi], bh[2 * g], bh[2 * g + 1]);
                    mma_bf16(c3[mi][g], ahi[mi], bl[2 * g], bl[2 * g + 1]);
                }
        }
    }

    // ---- epilogue: h = silu(c1)*c3 -> bf16 hi/lo ----
    int trow = lane >> 2, tc2 = (lane & 3) * 2;
#pragma unroll
    for (int mi = 0; mi < 2; ++mi) {
#pragma unroll
        for (int h8 = 0; h8 < 2; ++h8) {
            int row = mt * 128 + wm * 32 + mi * 16 + trow + h8 * 8;
            if (row < M) {
                size_t orow = (size_t)(base + row) * IDIM + nt * 64 + wn * 32;
#pragma unroll
                for (int g = 0; g < 4; ++g) {
                    float f1a = c1[mi][g][h8 * 2 + 0], f1b = c1[mi][g][h8 * 2 + 1];
                    float f3a = c3[mi][g][h8 * 2 + 0], f3b = c3[mi][g][h8 * 2 + 1];
                    float ha = f1a / (1.f + expf(-f1a)) * f3a;
                    float hb = f1b / (1.f + expf(-f1b)) * f3b;
                    uint32_t hi, lo; split2(ha, hb, hi, lo);
                    *(uint32_t*)(g_h_hi + orow + g * 8 + tc2) = hi;
                    *(uint32_t*)(g_h_lo + orow + g * 8 + tc2) = lo;
                }
            }
        }
    }
}

// -------- GEMM2: y = (h @ w2) * wt -> slot scatter --------
__global__ void __launch_bounds__(256, 2)
k_gemm2_mma(const float* __restrict__ w2g) {
    extern __shared__ __align__(16) unsigned char smem[];
    int e = blockIdx.z, mt = blockIdx.y, nt = blockIdx.x;
    int M = g_counts[e];
    if (mt * 128 >= M) return;
    int base = g_offsets[e];
    int tid = threadIdx.x;
    uint32_t sb = smem_u32(smem);

    const float* W2 = w2g + (size_t)e * IDIM * HDIM;   // [I=K, H=N] row-major

    // A loader (cp.async from g_h hi/lo)
    int arow = tid >> 1;
    int acg  = (tid & 1) * 16;
    int agr  = mt * 128 + arow;
    uint32_t aSz = (agr < M) ? 16u : 0u;
    size_t aGbase = (size_t)(base + agr) * IDIM + acg;
    uint32_t aOff = (uint32_t)(arow * AST + acg * 2);

    // B loader (fp32 w2, reg prefetch)
    int bk0 = tid >> 4,         bc0 = (tid & 15) * 4;
    int bk1 = (tid + 256) >> 4, bc1 = (tid & 15) * 4;
    uint32_t bO0 = (uint32_t)(bk0 * BST + bc0 * 2);
    uint32_t bO1 = (uint32_t)(bk1 * BST + bc1 * 2);

    int wid = tid >> 5, lane = tid & 31;
    int wm = wid >> 1, wn = wid & 1;
    uint32_t aFragOff = (uint32_t)((wm * 32 + (lane & 15)) * AST + (lane >> 4) * 16);
    uint32_t bFragOff = (uint32_t)(((lane & 7) + ((lane >> 3) & 1) * 8) * BST
                                   + (wn * 32 + ((lane >> 4) & 1) * 8) * 2);

    float c[2][4][4];
#pragma unroll
    for (int i = 0; i < 2; ++i)
#pragma unroll
        for (int g = 0; g < 4; ++g)
#pragma unroll
            for (int r = 0; r < 4; ++r) c[i][g][r] = 0.f;

    float4 bv0, bv1;

    // ---- prologue: B(0) regs, A(0) cp.async ----
    {
        size_t g0 = (size_t)bk0 * HDIM + nt * 64 + bc0;
        size_t g1 = (size_t)bk1 * HDIM + nt * 64 + bc1;
        bv0 = *(const float4*)(W2 + g0); bv1 = *(const float4*)(W2 + g1);
        uint32_t st = sb;
        CP16Z(st + aOff,             g_h_hi + aGbase,     aSz);
        CP16Z(st + aOff + 16,        g_h_hi + aGbase + 8, aSz);
        CP16Z(st + G1_A + aOff,      g_h_lo + aGbase,     aSz);
        CP16Z(st + G1_A + aOff + 16, g_h_lo + aGbase + 8, aSz);
        CP_COMMIT();
    }

    const int NC = IDIM / 32;
    for (int cc = 0; cc < NC; ++cc) {
        uint32_t stg = (uint32_t)(cc & 1) * G2_STAGE;
        unsigned char* st = smem + stg;
        // STS B(cc)
        {
            unsigned char* bh = st + 2 * G1_A;
            unsigned char* bl = bh + G_B;
            uint2 h, l;
            split4(bv0, h, l); *(uint2*)(bh + bO0) = h; *(uint2*)(bl + bO0) = l;
            split4(bv1, h, l); *(uint2*)(bh + bO1) = h; *(uint2*)(bl + bO1) = l;
        }
        CP_WAIT0();
        __syncthreads();
        if (cc + 1 < NC) {
            int k1 = (cc + 1) * 32;
            size_t g0 = (size_t)(k1 + bk0) * HDIM + nt * 64 + bc0;
            size_t g1 = (size_t)(k1 + bk1) * HDIM + nt * 64 + bc1;
            bv0 = *(const float4*)(W2 + g0); bv1 = *(const float4*)(W2 + g1);
            uint32_t nst = sb + (uint32_t)((cc + 1) & 1) * G2_STAGE;
            CP16Z(nst + aOff,             g_h_hi + aGbase + k1,     aSz);
            CP16Z(nst + aOff + 16,        g_h_hi + aGbase + k1 + 8, aSz);
            CP16Z(nst + G1_A + aOff,      g_h_lo + aGbase + k1,     aSz);
            CP16Z(nst + G1_A + aOff + 16, g_h_lo + aGbase + k1 + 8, aSz);
            CP_COMMIT();
        }
        uint32_t aLdHi = sb + stg + aFragOff;
        uint32_t aLdLo = sb + stg + G1_A + aFragOff;
        uint32_t bLdH  = sb + stg + 2 * G1_A + bFragOff;
        uint32_t bLdL  = bLdH + G_B;
#pragma unroll
        for (int ks = 0; ks < 2; ++ks) {
            uint32_t kof = ks * 16 * BST;
            uint32_t ahi[2][4], alo[2][4];
            LDMX4(ahi[0][0], ahi[0][1], ahi[0][2], ahi[0][3], aLdHi + ks * 32);
            LDMX4(ahi[1][0], ahi[1][1], ahi[1][2], ahi[1][3], aLdHi + 16 * AST + ks * 32);
            LDMX4(alo[0][0], alo[0][1], alo[0][2], alo[0][3], aLdLo + ks * 32);
            LDMX4(alo[1][0], alo[1][1], alo[1][2], alo[1][3], aLdLo + 16 * AST + ks * 32);
            uint32_t bh[8], bl[8];
            LDMX4T(bh[0], bh[1], bh[2], bh[3], bLdH + kof);
            LDMX4T(bh[4], bh[5], bh[6], bh[7], bLdH + kof + 32);
            LDMX4T(bl[0], bl[1], bl[2], bl[3], bLdL + kof);
            LDMX4T(bl[4], bl[5], bl[6], bl[7], bLdL + kof + 32);
#pragma unroll
            for (int mi = 0; mi < 2; ++mi)
#pragma unroll
                for (int g = 0; g < 4; ++g) {
                    mma_bf16(c[mi][g], ahi[mi], bh[2 * g], bh[2 * g + 1]);
                    mma_bf16(c[mi][g], alo[mi], bh[2 * g], bh[2 * g + 1]);
                    mma_bf16(c[mi][g], ahi[mi], bl[2 * g], bl[2 * g + 1]);
                }
        }
    }

    // ---- epilogue: scale by routing weight, scatter to slot buffer ----
    int trow = lane >> 2, tc2 = (lane & 3) * 2;
#pragma unroll
    for (int mi = 0; mi < 2; ++mi) {
#pragma unroll
        for (int h8 = 0; h8 < 2; ++h8) {
            int row = mt * 128 + wm * 32 + mi * 16 + trow + h8 * 8;
            if (row < M) {
                int ridx = e * T_TOK + row;
                int tok = g_tok[ridx]; float wt = g_wt[ridx]; int slot = g_slot[ridx];
                float* op = g_slotbuf + (size_t)slot * T_TOK * HDIM
                            + (size_t)tok * HDIM + nt * 64 + wn * 32;
#pragma unroll
                for (int g = 0; g < 4; ++g) {
                    float2 v;
                    v.x = wt * c[mi][g][h8 * 2 + 0];
                    v.y = wt * c[mi][g][h8 * 2 + 1];
                    *(float2*)(op + g * 8 + tc2) = v;
                }
            }
        }
    }
}

// ================= combine =================
__global__ void k_combine(float* __restrict__ out) {
    size_t i = (size_t)blockIdx.x * blockDim.x + threadIdx.x;
    size_t n4 = (size_t)T_TOK * HDIM / 4;
    if (i >= n4) return;
    const float4* s0 = (const float4*)g_slotbuf;
    const float4* s1 = (const float4*)(g_slotbuf + (size_t)T_TOK * HDIM);
    float4 a = s0[i], b = s1[i];
    float4 r;
    r.x = a.x + b.x; r.y = a.y + b.y; r.z = a.z + b.z; r.w = a.w + b.w;
    ((float4*)out)[i] = r;
}

// ================= launcher =================
extern "C" void kernel_launch(void* const* d_in, const int* in_sizes, int n_in,
                              void* d_out, int out_size) {
    const float* x  = (const float*)d_in[0];
    const float* gw = (const float*)d_in[1];
    const float* gb = (const float*)d_in[2];
    const float* w1 = (const float*)d_in[3];
    const float* w3 = (const float*)d_in[4];
    const float* w2 = (const float*)d_in[5];
    float* out = (float*)d_out;

    static int configured = 0;
    if (!configured) {
        cudaFuncSetAttribute(k_gemm1_mma, cudaFuncAttributeMaxDynamicSharedMemorySize, G1_TOTAL);
        cudaFuncSetAttribute(k_gemm2_mma, cudaFuncAttributeMaxDynamicSharedMemorySize, G2_TOTAL);
        configured = 1;
    }

    k_zero_counts<<<1, 32>>>();
    k_gate<<<(T_TOK * 32 + 255) / 256, 256>>>(x, gw, gb);
    k_offsets<<<1, 32>>>();

    dim3 g1(IDIM / 64, T_TOK / 128, NEXP);   // (32, 16, 8)
    k_gemm1_mma<<<g1, 256, G1_TOTAL>>>(x, w1, w3);

    dim3 g2(HDIM / 64, T_TOK / 128, NEXP);   // (16, 16, 8)
    k_gemm2_mma<<<g2, 256, G2_TOTAL>>>(w2);

    size_t n4 = (size_t)T_TOK * HDIM / 4;
    k_combine<<<(unsigned)((n4 + 255) / 256), 256>>>(out);
}

// round 8
// speedup vs baseline: 2.5175x; 1.0024x over previous
#include <cuda_runtime.h>
#include <cuda_bf16.h>
#include <cstdint>
#include <math.h>

// dims
#define T_TOK 2048
#define HDIM  1024
#define IDIM  2048
#define NEXP  8

// ================= device scratch =================
__device__ int   g_counts[NEXP];
__device__ int   g_tok [NEXP * T_TOK];
__device__ float g_wt  [NEXP * T_TOK];
__device__ int   g_slot[NEXP * T_TOK];

// pre-split weights, SAME layout as source (no transpose):
// w1/w3: [E][H][I]  (K-major rows = N-contiguous)   w2: [E][I][H]
__device__ __nv_bfloat16 g_w1hi[(size_t)NEXP * HDIM * IDIM];
__device__ __nv_bfloat16 g_w1lo[(size_t)NEXP * HDIM * IDIM];
__device__ __nv_bfloat16 g_w3hi[(size_t)NEXP * HDIM * IDIM];
__device__ __nv_bfloat16 g_w3lo[(size_t)NEXP * HDIM * IDIM];
__device__ __nv_bfloat16 g_w2hi[(size_t)NEXP * IDIM * HDIM];
__device__ __nv_bfloat16 g_w2lo[(size_t)NEXP * IDIM * HDIM];

// intermediate h (packed routed rows), pre-split to bf16 hi/lo
__device__ __nv_bfloat16 g_h_hi[(size_t)2 * T_TOK * IDIM];
__device__ __nv_bfloat16 g_h_lo[(size_t)2 * T_TOK * IDIM];
__device__ float g_slotbuf[(size_t)2 * T_TOK * HDIM];

// ================= helpers =================
__device__ __forceinline__ uint32_t smem_u32(const void* p) {
    uint32_t a;
    asm("{ .reg .u64 t; cvta.to.shared.u64 t, %1; cvt.u32.u64 %0, t; }" : "=r"(a) : "l"(p));
    return a;
}

#define LDMX4(r0, r1, r2, r3, addr)                                              \
    asm volatile("ldmatrix.sync.aligned.m8n8.x4.shared.b16 {%0,%1,%2,%3}, [%4];" \
                 : "=r"(r0), "=r"(r1), "=r"(r2), "=r"(r3) : "r"(addr))

#define LDMX4T(r0, r1, r2, r3, addr)                                                   \
    asm volatile("ldmatrix.sync.aligned.m8n8.x4.trans.shared.b16 {%0,%1,%2,%3}, [%4];" \
                 : "=r"(r0), "=r"(r1), "=r"(r2), "=r"(r3) : "r"(addr))

#define CP16(dst, src) \
    asm volatile("cp.async.cg.shared.global [%0], [%1], 16;" :: "r"(dst), "l"(src))
#define CP16Z(dst, src, sz) \
    asm volatile("cp.async.cg.shared.global [%0], [%1], 16, %2;" :: "r"(dst), "l"(src), "r"(sz))
#define CP_COMMIT() asm volatile("cp.async.commit_group;" ::: "memory")
#define CP_WAIT0()  asm volatile("cp.async.wait_group 0;" ::: "memory")

__device__ __forceinline__ void mma_bf16(float* d, const uint32_t* a, uint32_t b0, uint32_t b1) {
    asm volatile(
        "mma.sync.aligned.m16n8k16.row.col.f32.bf16.bf16.f32 "
        "{%0,%1,%2,%3}, {%4,%5,%6,%7}, {%8,%9}, {%0,%1,%2,%3};"
        : "+f"(d[0]), "+f"(d[1]), "+f"(d[2]), "+f"(d[3])
        : "r"(a[0]), "r"(a[1]), "r"(a[2]), "r"(a[3]), "r"(b0), "r"(b1));
}

__device__ __forceinline__ void split2(float a, float b, uint32_t& hi, uint32_t& lo) {
    __nv_bfloat16 ha = __float2bfloat16_rn(a), hb = __float2bfloat16_rn(b);
    float ra = a - __bfloat162float(ha), rb = b - __bfloat162float(hb);
    __nv_bfloat162 hp; hp.x = ha; hp.y = hb;
    __nv_bfloat162 lp; lp.x = __float2bfloat16_rn(ra); lp.y = __float2bfloat16_rn(rb);
    hi = *(uint32_t*)&hp; lo = *(uint32_t*)&lp;
}

__device__ __forceinline__ void split4(const float4& v, uint2& hi, uint2& lo) {
    split2(v.x, v.y, hi.x, lo.x);
    split2(v.z, v.w, hi.y, lo.y);
}

// ================= streaming weight split (no transpose) =================
// All three weights have the same element count: 8*1024*2048 = 16,777,216.
__global__ void k_split_stream(const float* __restrict__ w1,
                               const float* __restrict__ w3,
                               const float* __restrict__ w2) {
    int z = blockIdx.y;
    const float* src = (z == 0) ? w1 : (z == 1) ? w3 : w2;
    __nv_bfloat16* dh = (z == 0) ? g_w1hi : (z == 1) ? g_w3hi : g_w2hi;
    __nv_bfloat16* dl = (z == 0) ? g_w1lo : (z == 1) ? g_w3lo : g_w2lo;
    size_t i = (size_t)blockIdx.x * blockDim.x + threadIdx.x;   // float4 index
    float4 v = ((const float4*)src)[i];
    uint2 h, l; split4(v, h, l);
    ((uint2*)dh)[i] = h;
    ((uint2*)dl)[i] = l;
}

// ================= gating =================
__global__ void k_zero_counts() { if (threadIdx.x < NEXP) g_counts[threadIdx.x] = 0; }

__global__ void k_gate(const float* __restrict__ x, const float* __restrict__ gw,
                       const float* __restrict__ gb) {
    int warp = (blockIdx.x * blockDim.x + threadIdx.x) >> 5;
    int lane = threadIdx.x & 31;
    if (warp >= T_TOK) return;
    const float* xr = x + (size_t)warp * HDIM;
    float acc[NEXP];
#pragma unroll
    for (int e = 0; e < NEXP; ++e) acc[e] = 0.f;
    for (int h = lane; h < HDIM; h += 32) {
        float xv = xr[h];
        const float4* g4 = (const float4*)(gw + (size_t)h * NEXP);
        float4 a = g4[0], b = g4[1];
        acc[0] += xv * a.x; acc[1] += xv * a.y; acc[2] += xv * a.z; acc[3] += xv * a.w;
        acc[4] += xv * b.x; acc[5] += xv * b.y; acc[6] += xv * b.z; acc[7] += xv * b.w;
    }
#pragma unroll
    for (int o = 16; o > 0; o >>= 1)
#pragma unroll
        for (int e = 0; e < NEXP; ++e) acc[e] += __shfl_xor_sync(0xffffffffu, acc[e], o);
    if (lane == 0) {
        float l[NEXP]; float m = -1e30f;
#pragma unroll
        for (int e = 0; e < NEXP; ++e) { l[e] = acc[e] + gb[e]; m = fmaxf(m, l[e]); }
        float p[NEXP];
#pragma unroll
        for (int e = 0; e < NEXP; ++e) p[e] = expf(l[e] - m);
        int i0 = 0;
#pragma unroll
        for (int e = 1; e < NEXP; ++e) if (p[e] > p[i0]) i0 = e;
        int i1 = (i0 == 0) ? 1 : 0;
#pragma unroll
        for (int e = 0; e < NEXP; ++e) if (e != i0 && p[e] > p[i1]) i1 = e;
        float s = p[i0] + p[i1];
        int p0 = atomicAdd(&g_counts[i0], 1);
        g_tok[i0 * T_TOK + p0] = warp; g_wt[i0 * T_TOK + p0] = p[i0] / s; g_slot[i0 * T_TOK + p0] = 0;
        int p1 = atomicAdd(&g_counts[i1], 1);
        g_tok[i1 * T_TOK + p1] = warp; g_wt[i1 * T_TOK + p1] = p[i1] / s; g_slot[i1 * T_TOK + p1] = 1;
    }
}

// ================= GEMM tiling =================
// CTA tile: 128(M) x 64(N), BK=32. 8 warps as 4(M) x 2(N); warp tile 32x32.
// A smem: [128 rows][32 bf16 + pad] stride 80 (row-major, LDMX4).
// B smem: [32 k-rows][64 bf16 + pad] stride 144 (n-contiguous, LDMX4T).
#define AST 80
#define BST 144
#define G1_A 10240            // 128*80
#define G_B  4608             // 32*144

#define G1_STAGE (2 * G1_A + 4 * G_B)   // 38912
#define G1_TOTAL (2 * G1_STAGE + 512)   // 78336
#define G2_STAGE (2 * G1_A + 2 * G_B)   // 29696
#define G2_TOTAL (2 * G2_STAGE)         // 59392

// -------- GEMM1: c1 = Xg @ w1, c3 = Xg @ w3 ; h = silu(c1)*c3 --------
__global__ void __launch_bounds__(256, 2)
k_gemm1_mma(const float* __restrict__ x) {
    extern __shared__ __align__(16) unsigned char smem[];
    __shared__ int sMB[2];
    int e = blockIdx.z, mt = blockIdx.y, nt = blockIdx.x;
    int tid = threadIdx.x;
    uint32_t sb = smem_u32(smem);

    // in-kernel offsets (replaces k_offsets launch)
    if (tid == 0) {
        int off = 0;
        for (int i = 0; i < NEXP; ++i) { if (i < e) off += g_counts[i]; }
        sMB[0] = g_counts[e]; sMB[1] = off;
    }
    int* toks = (int*)(smem + 2 * G1_STAGE);
    __syncthreads();
    int M = sMB[0], base = sMB[1];
    if (mt * 128 >= M) return;
    if (tid < 128) {
        int r = mt * 128 + tid;
        toks[tid] = (r < M) ? g_tok[e * T_TOK + r] : -1;
    }
    __syncthreads();

    size_t eoff = (size_t)e * HDIM * IDIM;
    const __nv_bfloat16* Bsrc[4] = { g_w1hi + eoff, g_w1lo + eoff,
                                     g_w3hi + eoff, g_w3lo + eoff };

    // A loader: 2 threads per row, each 16 fp32
    int arow = tid >> 1;
    int acg  = (tid & 1) * 16;
    int tokA = toks[arow];
    const float* xrow = (tokA >= 0) ? (x + (size_t)tokA * HDIM) : (const float*)0;
    uint32_t aOff = (uint32_t)(arow * AST + acg * 2);

    // B loader (cp.async): 4 arrays x 32 rows x 4 segs-of-16B -> 4 CP16/thread
    int brow = (tid >> 3) & 31;
    int bseg = tid & 7;
    uint32_t bDstOff = (uint32_t)(brow * BST + bseg * 16);
    size_t bSrcOff = (size_t)brow * IDIM + nt * 64 + bseg * 8;

    // mma indices
    int wid = tid >> 5, lane = tid & 31;
    int wm = wid >> 1, wn = wid & 1;
    uint32_t aFragOff = (uint32_t)((wm * 32 + (lane & 15)) * AST + (lane >> 4) * 16);
    uint32_t bFragOff = (uint32_t)(((lane & 7) + ((lane >> 3) & 1) * 8) * BST
                                   + (wn * 32 + ((lane >> 4) & 1) * 8) * 2);

    float c1[2][4][4], c3[2][4][4];
#pragma unroll
    for (int i = 0; i < 2; ++i)
#pragma unroll
        for (int g = 0; g < 4; ++g)
#pragma unroll
            for (int r = 0; r < 4; ++r) { c1[i][g][r] = 0.f; c3[i][g][r] = 0.f; }

    float4 av0, av1, av2, av3;
    // ---- prologue: A(0) regs, B(0) cp.async -> stage 0 ----
    if (xrow) {
        const float4* p = (const float4*)(xrow + acg);
        av0 = p[0]; av1 = p[1]; av2 = p[2]; av3 = p[3];
    } else av0 = av1 = av2 = av3 = make_float4(0.f, 0.f, 0.f, 0.f);
#pragma unroll
    for (int a4 = 0; a4 < 4; ++a4)
        CP16(sb + 2 * G1_A + a4 * G_B + bDstOff, Bsrc[a4] + bSrcOff);
    CP_COMMIT();

    const int NC = HDIM / 32;
    for (int c = 0; c < NC; ++c) {
        uint32_t stg = (uint32_t)(c & 1) * G1_STAGE;
        unsigned char* st = smem + stg;
        // ---- STS A(c) (split) ----
        {
            uint2 h0, l0, h1, l1, h2, l2, h3, l3;
            split4(av0, h0, l0); split4(av1, h1, l1);
            split4(av2, h2, l2); split4(av3, h3, l3);
            *(uint4*)(st + aOff)             = make_uint4(h0.x, h0.y, h1.x, h1.y);
            *(uint4*)(st + aOff + 16)        = make_uint4(h2.x, h2.y, h3.x, h3.y);
            *(uint4*)(st + G1_A + aOff)      = make_uint4(l0.x, l0.y, l1.x, l1.y);
            *(uint4*)(st + G1_A + aOff + 16) = make_uint4(l2.x, l2.y, l3.x, l3.y);
        }
        CP_WAIT0();
        __syncthreads();
        // ---- prefetch next chunk (safe: all warps past mma(c-1)) ----
        if (c + 1 < NC) {
            int k1 = (c + 1) * 32;
            if (xrow) {
                const float4* p = (const float4*)(xrow + k1 + acg);
                av0 = p[0]; av1 = p[1]; av2 = p[2]; av3 = p[3];
            }
            uint32_t nst = sb + (uint32_t)((c + 1) & 1) * G1_STAGE + 2 * G1_A;
            size_t so = bSrcOff + (size_t)k1 * IDIM;
#pragma unroll
            for (int a4 = 0; a4 < 4; ++a4)
                CP16(nst + a4 * G_B + bDstOff, Bsrc[a4] + so);
            CP_COMMIT();
        }
        // ---- mma on stage c ----
        uint32_t aLdHi = sb + stg + aFragOff;
        uint32_t aLdLo = sb + stg + G1_A + aFragOff;
        uint32_t bB1h  = sb + stg + 2 * G1_A + bFragOff;
        uint32_t bB1l  = bB1h + G_B;
        uint32_t bB3h  = bB1l + G_B;
        uint32_t bB3l  = bB3h + G_B;
#pragma unroll
        for (int ks = 0; ks < 2; ++ks) {
            uint32_t kof = ks * 16 * BST;
            uint32_t ahi[2][4], alo[2][4];
            LDMX4(ahi[0][0], ahi[0][1], ahi[0][2], ahi[0][3], aLdHi + ks * 32);
            LDMX4(ahi[1][0], ahi[1][1], ahi[1][2], ahi[1][3], aLdHi + 16 * AST + ks * 32);
            LDMX4(alo[0][0], alo[0][1], alo[0][2], alo[0][3], aLdLo + ks * 32);
            LDMX4(alo[1][0], alo[1][1], alo[1][2], alo[1][3], aLdLo + 16 * AST + ks * 32);

            uint32_t bh[8], bl[8];
            LDMX4T(bh[0], bh[1], bh[2], bh[3], bB1h + kof);
            LDMX4T(bh[4], bh[5], bh[6], bh[7], bB1h + kof + 32);
            LDMX4T(bl[0], bl[1], bl[2], bl[3], bB1l + kof);
            LDMX4T(bl[4], bl[5], bl[6], bl[7], bB1l + kof + 32);
#pragma unroll
            for (int mi = 0; mi < 2; ++mi)
#pragma unroll
                for (int g = 0; g < 4; ++g) {
                    mma_bf16(c1[mi][g], ahi[mi], bh[2 * g], bh[2 * g + 1]);
                    mma_bf16(c1[mi][g], alo[mi], bh[2 * g], bh[2 * g + 1]);
                    mma_bf16(c1[mi][g], ahi[mi], bl[2 * g], bl[2 * g + 1]);
                }
            LDMX4T(bh[0], bh[1], bh[2], bh[3], bB3h + kof);
            LDMX4T(bh[4], bh[5], bh[6], bh[7], bB3h + kof + 32);
            LDMX4T(bl[0], bl[1], bl[2], bl[3], bB3l + kof);
            LDMX4T(bl[4], bl[5], bl[6], bl[7], bB3l + kof + 32);
#pragma unroll
            for (int mi = 0; mi < 2; ++mi)
#pragma unroll
                for (int g = 0; g < 4; ++g) {
                    mma_bf16(c3[mi][g], ahi[mi], bh[2 * g], bh[2 * g + 1]);
                    mma_bf16(c3[mi][g], alo[mi], bh[2 * g], bh[2 * g + 1]);
                    mma_bf16(c3[mi][g], ahi[mi], bl[2 * g], bl[2 * g + 1]);
                }
        }
    }

    // ---- epilogue: h = silu(c1)*c3 -> bf16 hi/lo ----
    int trow = lane >> 2, tc2 = (lane & 3) * 2;
#pragma unroll
    for (int mi = 0; mi < 2; ++mi) {
#pragma unroll
        for (int h8 = 0; h8 < 2; ++h8) {
            int row = mt * 128 + wm * 32 + mi * 16 + trow + h8 * 8;
            if (row < M) {
                size_t orow = (size_t)(base + row) * IDIM + nt * 64 + wn * 32;
#pragma unroll
                for (int g = 0; g < 4; ++g) {
                    float f1a = c1[mi][g][h8 * 2 + 0], f1b = c1[mi][g][h8 * 2 + 1];
                    float f3a = c3[mi][g][h8 * 2 + 0], f3b = c3[mi][g][h8 * 2 + 1];
                    float ha = f1a / (1.f + expf(-f1a)) * f3a;
                    float hb = f1b / (1.f + expf(-f1b)) * f3b;
                    uint32_t hi, lo; split2(ha, hb, hi, lo);
                    *(uint32_t*)(g_h_hi + orow + g * 8 + tc2) = hi;
                    *(uint32_t*)(g_h_lo + orow + g * 8 + tc2) = lo;
                }
            }
        }
    }
}

// -------- GEMM2: y = (h @ w2) * wt -> slot scatter --------
__global__ void __launch_bounds__(256, 2)
k_gemm2_mma() {
    extern __shared__ __align__(16) unsigned char smem[];
    __shared__ int sMB[2];
    int e = blockIdx.z, mt = blockIdx.y, nt = blockIdx.x;
    int tid = threadIdx.x;
    uint32_t sb = smem_u32(smem);

    if (tid == 0) {
        int off = 0;
        for (int i = 0; i < NEXP; ++i) { if (i < e) off += g_counts[i]; }
        sMB[0] = g_counts[e]; sMB[1] = off;
    }
    __syncthreads();
    int M = sMB[0], base = sMB[1];
    if (mt * 128 >= M) return;

    size_t eoff = (size_t)e * IDIM * HDIM;
    const __nv_bfloat16* W2h = g_w2hi + eoff;
    const __nv_bfloat16* W2l = g_w2lo + eoff;

    // A loader (cp.async from g_h hi/lo)
    int arow = tid >> 1;
    int acg  = (tid & 1) * 16;
    int agr  = mt * 128 + arow;
    uint32_t aSz = (agr < M) ? 16u : 0u;
    size_t aGbase = (size_t)(base + agr) * IDIM + acg;
    uint32_t aOff = (uint32_t)(arow * AST + acg * 2);

    // B loader (cp.async)
    int brow = (tid >> 3) & 31;
    int bseg = tid & 7;
    uint32_t bDstOff = (uint32_t)(brow * BST + bseg * 16);
    size_t bSrcOff = (size_t)brow * HDIM + nt * 64 + bseg * 8;

    int wid = tid >> 5, lane = tid & 31;
    int wm = wid >> 1, wn = wid & 1;
    uint32_t aFragOff = (uint32_t)((wm * 32 + (lane & 15)) * AST + (lane >> 4) * 16);
    uint32_t bFragOff = (uint32_t)(((lane & 7) + ((lane >> 3) & 1) * 8) * BST
                                   + (wn * 32 + ((lane >> 4) & 1) * 8) * 2);

    float c[2][4][4];
#pragma unroll
    for (int i = 0; i < 2; ++i)
#pragma unroll
        for (int g = 0; g < 4; ++g)
#pragma unroll
            for (int r = 0; r < 4; ++r) c[i][g][r] = 0.f;

    // ---- prologue: stage 0 ----
    {
        uint32_t st = sb;
        CP16Z(st + aOff,             g_h_hi + aGbase,     aSz);
        CP16Z(st + aOff + 16,        g_h_hi + aGbase + 8, aSz);
        CP16Z(st + G1_A + aOff,      g_h_lo + aGbase,     aSz);
        CP16Z(st + G1_A + aOff + 16, g_h_lo + aGbase + 8, aSz);
        CP16(st + 2 * G1_A + bDstOff,       W2h + bSrcOff);
        CP16(st + 2 * G1_A + G_B + bDstOff, W2l + bSrcOff);
        CP_COMMIT();
    }

    const int NC = IDIM / 32;
    for (int cc = 0; cc < NC; ++cc) {
        uint32_t stg = (uint32_t)(cc & 1) * G2_STAGE;
        CP_WAIT0();
        __syncthreads();
        if (cc + 1 < NC) {
            int k1 = (cc + 1) * 32;
            uint32_t nst = sb + (uint32_t)((cc + 1) & 1) * G2_STAGE;
            CP16Z(nst + aOff,             g_h_hi + aGbase + k1,     aSz);
            CP16Z(nst + aOff + 16,        g_h_hi + aGbase + k1 + 8, aSz);
            CP16Z(nst + G1_A + aOff,      g_h_lo + aGbase + k1,     aSz);
            CP16Z(nst + G1_A + aOff + 16, g_h_lo + aGbase + k1 + 8, aSz);
            size_t so = bSrcOff + (size_t)k1 * HDIM;
            CP16(nst + 2 * G1_A + bDstOff,       W2h + so);
            CP16(nst + 2 * G1_A + G_B + bDstOff, W2l + so);
            CP_COMMIT();
        }
        uint32_t aLdHi = sb + stg + aFragOff;
        uint32_t aLdLo = sb + stg + G1_A + aFragOff;
        uint32_t bLdH  = sb + stg + 2 * G1_A + bFragOff;
        uint32_t bLdL  = bLdH + G_B;
#pragma unroll
        for (int ks = 0; ks < 2; ++ks) {
            uint32_t kof = ks * 16 * BST;
            uint32_t ahi[2][4], alo[2][4];
            LDMX4(ahi[0][0], ahi[0][1], ahi[0][2], ahi[0][3], aLdHi + ks * 32);
            LDMX4(ahi[1][0], ahi[1][1], ahi[1][2], ahi[1][3], aLdHi + 16 * AST + ks * 32);
            LDMX4(alo[0][0], alo[0][1], alo[0][2], alo[0][3], aLdLo + ks * 32);
            LDMX4(alo[1][0], alo[1][1], alo[1][2], alo[1][3], aLdLo + 16 * AST + ks * 32);
            uint32_t bh[8], bl[8];
            LDMX4T(bh[0], bh[1], bh[2], bh[3], bLdH + kof);
            LDMX4T(bh[4], bh[5], bh[6], bh[7], bLdH + kof + 32);
            LDMX4T(bl[0], bl[1], bl[2], bl[3], bLdL + kof);
            LDMX4T(bl[4], bl[5], bl[6], bl[7], bLdL + kof + 32);
#pragma unroll
            for (int mi = 0; mi < 2; ++mi)
#pragma unroll
                for (int g = 0; g < 4; ++g) {
                    mma_bf16(c[mi][g], ahi[mi], bh[2 * g], bh[2 * g + 1]);
                    mma_bf16(c[mi][g], alo[mi], bh[2 * g], bh[2 * g + 1]);
                    mma_bf16(c[mi][g], ahi[mi], bl[2 * g], bl[2 * g + 1]);
                }
        }
    }

    // ---- epilogue: scale by routing weight, scatter to slot buffer ----
    int trow = lane >> 2, tc2 = (lane & 3) * 2;
#pragma unroll
    for (int mi = 0; mi < 2; ++mi) {
#pragma unroll
        for (int h8 = 0; h8 < 2; ++h8) {
            int row = mt * 128 + wm * 32 + mi * 16 + trow + h8 * 8;
            if (row < M) {
                int ridx = e * T_TOK + row;
                int tok = g_tok[ridx]; float wt = g_wt[ridx]; int slot = g_slot[ridx];
                float* op = g_slotbuf + (size_t)slot * T_TOK * HDIM
                            + (size_t)tok * HDIM + nt * 64 + wn * 32;
#pragma unroll
                for (int g = 0; g < 4; ++g) {
                    float2 v;
                    v.x = wt * c[mi][g][h8 * 2 + 0];
                    v.y = wt * c[mi][g][h8 * 2 + 1];
                    *(float2*)(op + g * 8 + tc2) = v;
                }
            }
        }
    }
}

// ================= combine =================
__global__ void k_combine(float* __restrict__ out) {
    size_t i = (size_t)blockIdx.x * blockDim.x + threadIdx.x;
    size_t n4 = (size_t)T_TOK * HDIM / 4;
    if (i >= n4) return;
    const float4* s0 = (const float4*)g_slotbuf;
    const float4* s1 = (const float4*)(g_slotbuf + (size_t)T_TOK * HDIM);
    float4 a = s0[i], b = s1[i];
    float4 r;
    r.x = a.x + b.x; r.y = a.y + b.y; r.z = a.z + b.z; r.w = a.w + b.w;
    ((float4*)out)[i] = r;
}

// ================= launcher =================
extern "C" void kernel_launch(void* const* d_in, const int* in_sizes, int n_in,
                              void* d_out, int out_size) {
    const float* x  = (const float*)d_in[0];
    const float* gw = (const float*)d_in[1];
    const float* gb = (const float*)d_in[2];
    const float* w1 = (const float*)d_in[3];
    const float* w3 = (const float*)d_in[4];
    const float* w2 = (const float*)d_in[5];
    float* out = (float*)d_out;

    static int configured = 0;
    if (!configured) {
        cudaFuncSetAttribute(k_gemm1_mma, cudaFuncAttributeMaxDynamicSharedMemorySize, G1_TOTAL);
        cudaFuncSetAttribute(k_gemm2_mma, cudaFuncAttributeMaxDynamicSharedMemorySize, G2_TOTAL);
        configured = 1;
    }

    // 1: weight split (streaming, no transpose)
    {
        dim3 g((HDIM * IDIM * NEXP / 4) / 256, 3);   // (16384, 3)
        k_split_stream<<<g, 256>>>(w1, w3, w2);
    }
    // 2-3: gating
    k_zero_counts<<<1, 32>>>();
    k_gate<<<(T_TOK * 32 + 255) / 256, 256>>>(x, gw, gb);

    // 4: GEMM1 (ncu capture slot)
    dim3 g1(IDIM / 64, T_TOK / 128, NEXP);   // (32, 16, 8)
    k_gemm1_mma<<<g1, 256, G1_TOTAL>>>(x);

    // 5: GEMM2
    dim3 g2(HDIM / 64, T_TOK / 128, NEXP);   // (16, 16, 8)
    k_gemm2_mma<<<g2, 256, G2_TOTAL>>>();

    // 6: combine
    size_t n4 = (size_t)T_TOK * HDIM / 4;
    k_combine<<<(unsigned)((n4 + 255) / 256), 256>>>(out);
}